// round 1
// baseline (speedup 1.0000x reference)
#include <cuda_runtime.h>

// Shapes are fixed by the problem: B=2, S=2048, E=1024, H=16, D=64.
static constexpr int E   = 1024;
static constexpr int NHD = 16;
static constexpr int HD  = 64;
static constexpr int B   = 2;
static constexpr int S   = 2048;
static constexpr int BS  = B * S;      // 4096 tokens
static constexpr int E3  = 3 * E;      // 3072

// Scratch (no allocs allowed in kernel_launch): qkv 48 MB, attention out 16 MB.
__device__ float g_qkv[(size_t)BS * E3];
__device__ float g_y[(size_t)BS * E];

// ---------------------------------------------------------------------------
// SGEMM: C[M,N] = A[M,K] @ Bm[K,N], row-major. Tiles 128x64, BK=16.
// 256 threads, 8x4 micro-tile per thread. M%128==0, N%64==0, K%16==0 assumed.
// ---------------------------------------------------------------------------
__global__ __launch_bounds__(256) void sgemm_kernel(
    const float* __restrict__ A, const float* __restrict__ Bm,
    float* __restrict__ C, int M, int N, int K)
{
    __shared__ float As[16][132];  // A tile transposed: As[k][row], pad for banks
    __shared__ float Bs[16][68];   // B tile: Bs[k][col]

    const int tid = threadIdx.x;
    const int ty  = tid >> 4;      // 0..15 -> 8 rows each
    const int tx  = tid & 15;      // 0..15 -> 4 cols each
    const int brow = blockIdx.y * 128;
    const int bcol = blockIdx.x * 64;

    // Global-load mapping
    const int ar  = tid >> 2;          // 0..63 (A rows, +64 for second half)
    const int ac4 = (tid & 3) << 2;    // 0,4,8,12 (A k-cols)
    const int bk  = tid >> 4;          // 0..15  (B k-row)
    const int bc4 = (tid & 15) << 2;   // 0..60  (B cols)

    float acc[8][4];
    #pragma unroll
    for (int i = 0; i < 8; i++)
        #pragma unroll
        for (int j = 0; j < 4; j++) acc[i][j] = 0.f;

    for (int k0 = 0; k0 < K; k0 += 16) {
        float4 va0 = *(const float4*)&A[(size_t)(brow + ar)      * K + k0 + ac4];
        float4 va1 = *(const float4*)&A[(size_t)(brow + ar + 64) * K + k0 + ac4];
        float4 vb  = *(const float4*)&Bm[(size_t)(k0 + bk) * N + bcol + bc4];

        As[ac4 + 0][ar] = va0.x; As[ac4 + 1][ar] = va0.y;
        As[ac4 + 2][ar] = va0.z; As[ac4 + 3][ar] = va0.w;
        As[ac4 + 0][ar + 64] = va1.x; As[ac4 + 1][ar + 64] = va1.y;
        As[ac4 + 2][ar + 64] = va1.z; As[ac4 + 3][ar + 64] = va1.w;
        *(float4*)&Bs[bk][bc4] = vb;
        __syncthreads();

        #pragma unroll
        for (int k = 0; k < 16; k++) {
            float4 a0 = *(const float4*)&As[k][ty * 8];
            float4 a1 = *(const float4*)&As[k][ty * 8 + 4];
            float4 b4 = *(const float4*)&Bs[k][tx * 4];
            float ar8[8] = {a0.x, a0.y, a0.z, a0.w, a1.x, a1.y, a1.z, a1.w};
            float br4[4] = {b4.x, b4.y, b4.z, b4.w};
            #pragma unroll
            for (int i = 0; i < 8; i++)
                #pragma unroll
                for (int j = 0; j < 4; j++)
                    acc[i][j] = fmaf(ar8[i], br4[j], acc[i][j]);
        }
        __syncthreads();
    }

    #pragma unroll
    for (int i = 0; i < 8; i++) {
        float4 o = make_float4(acc[i][0], acc[i][1], acc[i][2], acc[i][3]);
        *(float4*)&C[(size_t)(brow + ty * 8 + i) * N + bcol + tx * 4] = o;
    }
}

// ---------------------------------------------------------------------------
// Fused causal attention over one (b, h, 64-query tile) per block.
// Flash-style online softmax; 64x64 key tiles; K smem-transposed with
// 16B XOR swizzle (conflict-free float4 reads); V reuses the K buffer.
// scale 1/sqrt(64)=0.125 folded into Q on load.
// ---------------------------------------------------------------------------
__global__ __launch_bounds__(256) void attn_kernel(
    const float* __restrict__ qkv, float* __restrict__ y)
{
    __shared__ float Qt[64 * 64];   // Qt[d*64 + r]  (transposed)
    __shared__ float KVs[64 * 64];  // K phase: [d][swizzled c];  V phase: [c][d]
    __shared__ float Ps[64 * 64];   // probs [r][c]

    const int qt = blockIdx.x;      // query tile 0..31
    const int bh = blockIdx.y;      // 0..31
    const int b  = bh >> 4;
    const int h  = bh & 15;
    const int tid = threadIdx.x;
    const int ty  = tid >> 4;       // row group: rows ty*4..ty*4+3
    const int tx  = tid & 15;       // col group: cols tx*4..tx*4+3

    const float* base = qkv + (size_t)b * S * E3;
    const int hoff = h * HD;

    // Load Q tile transposed, scale folded in. (One-time; conflicts negligible.)
    for (int e = tid; e < 4096; e += 256) {
        const int d = e & 63, r = e >> 6;
        Qt[d * 64 + r] = base[(size_t)(qt * 64 + r) * E3 + hoff + d] * 0.125f;
    }

    float acc[4][4];
    float m_i[4], l_i[4];
    #pragma unroll
    for (int i = 0; i < 4; i++) {
        m_i[i] = -1e30f; l_i[i] = 0.f;
        #pragma unroll
        for (int j = 0; j < 4; j++) acc[i][j] = 0.f;
    }

    for (int kt = 0; kt <= qt; kt++) {
        __syncthreads();  // prior V reads (and first-iter Q load) complete
        // K tile, transposed into smem with 16B-block XOR swizzle
        for (int e = tid; e < 4096; e += 256) {
            const int d = e & 63, c = e >> 6;
            KVs[d * 64 + ((((c >> 2) ^ (d & 15)) << 2) | (c & 3))] =
                base[(size_t)(kt * 64 + c) * E3 + E + hoff + d];
        }
        __syncthreads();

        // S = (Q*scale) @ K^T : outer product over d
        float s[4][4];
        #pragma unroll
        for (int i = 0; i < 4; i++)
            #pragma unroll
            for (int j = 0; j < 4; j++) s[i][j] = 0.f;

        #pragma unroll 8
        for (int d = 0; d < 64; d++) {
            float4 qb = *(const float4*)&Qt[d * 64 + ty * 4];
            float4 kb = *(const float4*)&KVs[d * 64 + ((tx ^ (d & 15)) << 2)];
            float qa[4] = {qb.x, qb.y, qb.z, qb.w};
            float ka[4] = {kb.x, kb.y, kb.z, kb.w};
            #pragma unroll
            for (int i = 0; i < 4; i++)
                #pragma unroll
                for (int j = 0; j < 4; j++)
                    s[i][j] = fmaf(qa[i], ka[j], s[i][j]);
        }

        if (kt == qt) {  // causal mask on the diagonal tile
            #pragma unroll
            for (int i = 0; i < 4; i++)
                #pragma unroll
                for (int j = 0; j < 4; j++)
                    if (tx * 4 + j > ty * 4 + i) s[i][j] = -1e30f;
        }

        // Online softmax per row (row owned by the 16 tx-lanes sharing ty)
        #pragma unroll
        for (int i = 0; i < 4; i++) {
            float mx = fmaxf(fmaxf(s[i][0], s[i][1]), fmaxf(s[i][2], s[i][3]));
            #pragma unroll
            for (int o = 8; o >= 1; o >>= 1)
                mx = fmaxf(mx, __shfl_xor_sync(0xffffffffu, mx, o));
            const float mnew  = fmaxf(m_i[i], mx);
            const float alpha = __expf(m_i[i] - mnew);
            float rs = 0.f;
            #pragma unroll
            for (int j = 0; j < 4; j++) { s[i][j] = __expf(s[i][j] - mnew); rs += s[i][j]; }
            #pragma unroll
            for (int o = 8; o >= 1; o >>= 1)
                rs += __shfl_xor_sync(0xffffffffu, rs, o);
            l_i[i] = l_i[i] * alpha + rs;
            m_i[i] = mnew;
            #pragma unroll
            for (int j = 0; j < 4; j++) acc[i][j] *= alpha;
        }

        // Stash probs, then overwrite KVs with V tile (natural layout)
        #pragma unroll
        for (int i = 0; i < 4; i++)
            *(float4*)&Ps[(ty * 4 + i) * 64 + tx * 4] =
                make_float4(s[i][0], s[i][1], s[i][2], s[i][3]);
        __syncthreads();
        for (int e = tid; e < 4096; e += 256) {
            const int d = e & 63, c = e >> 6;
            KVs[c * 64 + d] = base[(size_t)(kt * 64 + c) * E3 + 2 * E + hoff + d];
        }
        __syncthreads();

        // acc += P @ V
        #pragma unroll 8
        for (int kc = 0; kc < 64; kc++) {
            float4 vb = *(const float4*)&KVs[kc * 64 + tx * 4];
            float pa[4];
            #pragma unroll
            for (int i = 0; i < 4; i++) pa[i] = Ps[(ty * 4 + i) * 64 + kc];
            float va[4] = {vb.x, vb.y, vb.z, vb.w};
            #pragma unroll
            for (int i = 0; i < 4; i++)
                #pragma unroll
                for (int j = 0; j < 4; j++)
                    acc[i][j] = fmaf(pa[i], va[j], acc[i][j]);
        }
    }

    // Normalize and write y[b, s, h*64 + d]
    #pragma unroll
    for (int i = 0; i < 4; i++) {
        const float inv = 1.f / l_i[i];
        float4 o = make_float4(acc[i][0] * inv, acc[i][1] * inv,
                               acc[i][2] * inv, acc[i][3] * inv);
        *(float4*)&y[(size_t)(b * S + qt * 64 + ty * 4 + i) * E + hoff + tx * 4] = o;
    }
}

// ---------------------------------------------------------------------------
extern "C" void kernel_launch(void* const* d_in, const int* in_sizes, int n_in,
                              void* d_out, int out_size)
{
    const float* x      = (const float*)d_in[0];
    const float* w_attn = (const float*)d_in[1];
    const float* w_proj = (const float*)d_in[2];
    float* out = (float*)d_out;

    float* qkv = nullptr;
    float* yb  = nullptr;
    cudaGetSymbolAddress((void**)&qkv, g_qkv);
    cudaGetSymbolAddress((void**)&yb,  g_y);

    // 1) qkv = x @ w_attn   [4096,3072]
    sgemm_kernel<<<dim3(E3 / 64, BS / 128), 256>>>(x, w_attn, qkv, BS, E3, E);
    // 2) fused causal attention -> y  [4096,1024]
    attn_kernel<<<dim3(S / 64, B * NHD), 256>>>(qkv, yb);
    // 3) out = y @ w_proj   [4096,1024]
    sgemm_kernel<<<dim3(E / 64, BS / 128), 256>>>(yb, w_proj, out, BS, E, E);
}

// round 4
// speedup vs baseline: 1.2474x; 1.2474x over previous
#include <cuda_runtime.h>
#include <cstdint>

// Shapes fixed by the problem: B=2, S=2048, E=1024, H=16, D=64.
static constexpr int E   = 1024;
static constexpr int NHD = 16;
static constexpr int HD  = 64;
static constexpr int B   = 2;
static constexpr int S   = 2048;
static constexpr int BS  = B * S;      // 4096 tokens
static constexpr int E3  = 3 * E;      // 3072

__device__ float g_qkv[(size_t)BS * E3];
__device__ float g_y[(size_t)BS * E];

// ---------------------------------------------------------------------------
// tf32 helpers (mma.sync is sm_80+ PTX: legal on the harness's compute_103
// target; tcgen05 is NOT — it needs sm_103a which this toolchain won't emit).
// ---------------------------------------------------------------------------
__device__ __forceinline__ uint32_t f2tf32(float f) {
    uint32_t u;
    asm("cvt.rna.tf32.f32 %0, %1;" : "=r"(u) : "f"(f));
    return u;
}

// D = A(16x8, row) @ B(8x8, col) + C, tf32 in / f32 out.
__device__ __forceinline__ void mma_tf32(float* c, uint32_t a0, uint32_t a1,
                                         uint32_t a2, uint32_t a3,
                                         uint32_t b0, uint32_t b1) {
    asm volatile(
        "mma.sync.aligned.m16n8k8.row.col.f32.tf32.tf32.f32 "
        "{%0,%1,%2,%3}, {%4,%5,%6,%7}, {%8,%9}, {%0,%1,%2,%3};"
        : "+f"(c[0]), "+f"(c[1]), "+f"(c[2]), "+f"(c[3])
        : "r"(a0), "r"(a1), "r"(a2), "r"(a3), "r"(b0), "r"(b1));
}

// ---------------------------------------------------------------------------
// Tensor-core tf32 GEMM: C[M,N] = A[M,K] @ Bm[K,N], row-major.
// CTA tile 128x128, BK=16, 256 threads = 8 warps (2m x 4n), warp tile 64x32.
//
// Smem layouts pack the 4 k-values a fragment lane needs into one float4:
//   A: element (m,k) -> float idx m*16 + ((k&3)^(m&3))*4 + (k>>2)
//   B: element (k,n) -> float idx n*16 + (((k&3)^(n&3)^((n>>2)&3)))*4 + (k>>2)
// so each fragment load is a single conflict-free LDS.128 that serves both
// k-steps of the BK=16 block. M%128==0, N%128==0, K%16==0 (all shapes comply).
// ---------------------------------------------------------------------------
__global__ __launch_bounds__(256) void gemm_mma(
    const float* __restrict__ A, const float* __restrict__ Bm,
    float* __restrict__ C, int M, int N, int K)
{
    __shared__ float As[2][128 * 16];
    __shared__ float Bs[2][128 * 16];

    const int tid  = threadIdx.x;
    const int wid  = tid >> 5;
    const int lane = tid & 31;
    const int g    = lane >> 2;      // groupID 0..7
    const int tig  = lane & 3;       // thread-in-group 0..3
    const int m0   = (wid >> 2) * 64;   // warp m-origin in tile
    const int n0   = (wid & 3) * 32;    // warp n-origin in tile
    const int brow = blockIdx.y * 128;
    const int bcol = blockIdx.x * 128;

    // Gmem load mapping
    const int ar = tid >> 1;                 // A row 0..127
    const int aq = (tid & 1) * 2;            // A k-quad 0/2 (+1 for second ld)
    const int bk = tid >> 4;                 // B k-row 0..15
    const int bn = (tid & 15) * 4;           // B n-base (+64 for second ld)

    float acc[4][4][4];
    #pragma unroll
    for (int mt = 0; mt < 4; mt++)
        #pragma unroll
        for (int nt = 0; nt < 4; nt++)
            #pragma unroll
            for (int i = 0; i < 4; i++) acc[mt][nt][i] = 0.f;

    const int nIter = K >> 4;
    float4 va[2], vb[2];

    // Prologue: tile 0 -> smem buf 0.
    {
        va[0] = *(const float4*)&A[(size_t)(brow + ar) * K + aq * 4];
        va[1] = *(const float4*)&A[(size_t)(brow + ar) * K + aq * 4 + 4];
        vb[0] = *(const float4*)&Bm[(size_t)bk * N + bcol + bn];
        vb[1] = *(const float4*)&Bm[(size_t)bk * N + bcol + bn + 64];
        #pragma unroll
        for (int h = 0; h < 2; h++) {
            const int q = aq + h;
            const float v[4] = {va[h].x, va[h].y, va[h].z, va[h].w};
            #pragma unroll
            for (int i = 0; i < 4; i++)
                *(uint32_t*)&As[0][ar * 16 + ((i ^ (ar & 3)) << 2) + q] = f2tf32(v[i]);
        }
        #pragma unroll
        for (int h = 0; h < 2; h++) {
            const int nb = bn + h * 64;
            const float v[4] = {vb[h].x, vb[h].y, vb[h].z, vb[h].w};
            #pragma unroll
            for (int i = 0; i < 4; i++) {
                const int n = nb + i;
                *(uint32_t*)&Bs[0][n * 16 + (((bk & 3) ^ i ^ ((n >> 2) & 3)) << 2) + (bk >> 2)]
                    = f2tf32(v[i]);
            }
        }
    }
    __syncthreads();

    for (int it = 0; it < nIter; ++it) {
        const int cur = it & 1;

        // Issue next tile's gmem loads early.
        const bool more = (it + 1) < nIter;
        if (more) {
            const int k0 = (it + 1) << 4;
            va[0] = *(const float4*)&A[(size_t)(brow + ar) * K + k0 + aq * 4];
            va[1] = *(const float4*)&A[(size_t)(brow + ar) * K + k0 + aq * 4 + 4];
            vb[0] = *(const float4*)&Bm[(size_t)(k0 + bk) * N + bcol + bn];
            vb[1] = *(const float4*)&Bm[(size_t)(k0 + bk) * N + bcol + bn + 64];
        }

        // B fragments: one LDS.128 per n-tile covers both k-steps.
        float4 bF[4];
        #pragma unroll
        for (int nt = 0; nt < 4; nt++) {
            const int n = n0 + nt * 8 + g;
            bF[nt] = *(const float4*)&Bs[cur][n * 16 + ((tig ^ (n & 3) ^ ((n >> 2) & 3)) << 2)];
        }

        #pragma unroll
        for (int mt = 0; mt < 4; mt++) {
            const int ma = m0 + mt * 16 + g;
            const int mb = ma + 8;
            float4 aR0 = *(const float4*)&As[cur][ma * 16 + ((tig ^ (ma & 3)) << 2)];
            float4 aR1 = *(const float4*)&As[cur][mb * 16 + ((tig ^ (mb & 3)) << 2)];
            // k-step 0: components x (k=tig), y (k=tig+4)
            #pragma unroll
            for (int nt = 0; nt < 4; nt++)
                mma_tf32(acc[mt][nt],
                         __float_as_uint(aR0.x), __float_as_uint(aR1.x),
                         __float_as_uint(aR0.y), __float_as_uint(aR1.y),
                         __float_as_uint(bF[nt].x), __float_as_uint(bF[nt].y));
            // k-step 1: components z (k=tig+8), w (k=tig+12)
            #pragma unroll
            for (int nt = 0; nt < 4; nt++)
                mma_tf32(acc[mt][nt],
                         __float_as_uint(aR0.z), __float_as_uint(aR1.z),
                         __float_as_uint(aR0.w), __float_as_uint(aR1.w),
                         __float_as_uint(bF[nt].z), __float_as_uint(bF[nt].w));
        }

        if (more) {
            const int nxt = cur ^ 1;
            #pragma unroll
            for (int h = 0; h < 2; h++) {
                const int q = aq + h;
                const float v[4] = {va[h].x, va[h].y, va[h].z, va[h].w};
                #pragma unroll
                for (int i = 0; i < 4; i++)
                    *(uint32_t*)&As[nxt][ar * 16 + ((i ^ (ar & 3)) << 2) + q] = f2tf32(v[i]);
            }
            #pragma unroll
            for (int h = 0; h < 2; h++) {
                const int nb = bn + h * 64;
                const float v[4] = {vb[h].x, vb[h].y, vb[h].z, vb[h].w};
                #pragma unroll
                for (int i = 0; i < 4; i++) {
                    const int n = nb + i;
                    *(uint32_t*)&Bs[nxt][n * 16 + (((bk & 3) ^ i ^ ((n >> 2) & 3)) << 2) + (bk >> 2)]
                        = f2tf32(v[i]);
                }
            }
        }
        __syncthreads();
    }

    // Epilogue: c0,c1 -> (row g, cols 2tig,2tig+1); c2,c3 -> row g+8.
    #pragma unroll
    for (int mt = 0; mt < 4; mt++) {
        #pragma unroll
        for (int nt = 0; nt < 4; nt++) {
            const int r0 = brow + m0 + mt * 16 + g;
            const int cc = bcol + n0 + nt * 8 + 2 * tig;
            *(float2*)&C[(size_t)r0 * N + cc] =
                make_float2(acc[mt][nt][0], acc[mt][nt][1]);
            *(float2*)&C[(size_t)(r0 + 8) * N + cc] =
                make_float2(acc[mt][nt][2], acc[mt][nt][3]);
        }
    }
}

// ---------------------------------------------------------------------------
// Fused causal attention (unchanged): one (b, h, 64-query tile) per block.
// ---------------------------------------------------------------------------
__global__ __launch_bounds__(256) void attn_kernel(
    const float* __restrict__ qkv, float* __restrict__ y)
{
    __shared__ float Qt[64 * 64];
    __shared__ float KVs[64 * 64];
    __shared__ float Ps[64 * 64];

    const int qt = blockIdx.x;
    const int bh = blockIdx.y;
    const int b  = bh >> 4;
    const int h  = bh & 15;
    const int tid = threadIdx.x;
    const int ty  = tid >> 4;
    const int tx  = tid & 15;

    const float* base = qkv + (size_t)b * S * E3;
    const int hoff = h * HD;

    for (int e = tid; e < 4096; e += 256) {
        const int d = e & 63, r = e >> 6;
        Qt[d * 64 + r] = base[(size_t)(qt * 64 + r) * E3 + hoff + d] * 0.125f;
    }

    float acc[4][4];
    float m_i[4], l_i[4];
    #pragma unroll
    for (int i = 0; i < 4; i++) {
        m_i[i] = -1e30f; l_i[i] = 0.f;
        #pragma unroll
        for (int j = 0; j < 4; j++) acc[i][j] = 0.f;
    }

    for (int kt = 0; kt <= qt; kt++) {
        __syncthreads();
        for (int e = tid; e < 4096; e += 256) {
            const int d = e & 63, c = e >> 6;
            KVs[d * 64 + ((((c >> 2) ^ (d & 15)) << 2) | (c & 3))] =
                base[(size_t)(kt * 64 + c) * E3 + E + hoff + d];
        }
        __syncthreads();

        float s[4][4];
        #pragma unroll
        for (int i = 0; i < 4; i++)
            #pragma unroll
            for (int j = 0; j < 4; j++) s[i][j] = 0.f;

        #pragma unroll 8
        for (int d = 0; d < 64; d++) {
            float4 qb = *(const float4*)&Qt[d * 64 + ty * 4];
            float4 kb = *(const float4*)&KVs[d * 64 + ((tx ^ (d & 15)) << 2)];
            float qa[4] = {qb.x, qb.y, qb.z, qb.w};
            float ka[4] = {kb.x, kb.y, kb.z, kb.w};
            #pragma unroll
            for (int i = 0; i < 4; i++)
                #pragma unroll
                for (int j = 0; j < 4; j++)
                    s[i][j] = fmaf(qa[i], ka[j], s[i][j]);
        }

        if (kt == qt) {
            #pragma unroll
            for (int i = 0; i < 4; i++)
                #pragma unroll
                for (int j = 0; j < 4; j++)
                    if (tx * 4 + j > ty * 4 + i) s[i][j] = -1e30f;
        }

        #pragma unroll
        for (int i = 0; i < 4; i++) {
            float mx = fmaxf(fmaxf(s[i][0], s[i][1]), fmaxf(s[i][2], s[i][3]));
            #pragma unroll
            for (int o = 8; o >= 1; o >>= 1)
                mx = fmaxf(mx, __shfl_xor_sync(0xffffffffu, mx, o));
            const float mnew  = fmaxf(m_i[i], mx);
            const float alpha = __expf(m_i[i] - mnew);
            float rs = 0.f;
            #pragma unroll
            for (int j = 0; j < 4; j++) { s[i][j] = __expf(s[i][j] - mnew); rs += s[i][j]; }
            #pragma unroll
            for (int o = 8; o >= 1; o >>= 1)
                rs += __shfl_xor_sync(0xffffffffu, rs, o);
            l_i[i] = l_i[i] * alpha + rs;
            m_i[i] = mnew;
            #pragma unroll
            for (int j = 0; j < 4; j++) acc[i][j] *= alpha;
        }

        #pragma unroll
        for (int i = 0; i < 4; i++)
            *(float4*)&Ps[(ty * 4 + i) * 64 + tx * 4] =
                make_float4(s[i][0], s[i][1], s[i][2], s[i][3]);
        __syncthreads();
        for (int e = tid; e < 4096; e += 256) {
            const int d = e & 63, c = e >> 6;
            KVs[c * 64 + d] = base[(size_t)(kt * 64 + c) * E3 + 2 * E + hoff + d];
        }
        __syncthreads();

        #pragma unroll 8
        for (int kc = 0; kc < 64; kc++) {
            float4 vb = *(const float4*)&KVs[kc * 64 + tx * 4];
            float pa[4];
            #pragma unroll
            for (int i = 0; i < 4; i++) pa[i] = Ps[(ty * 4 + i) * 64 + kc];
            float va[4] = {vb.x, vb.y, vb.z, vb.w};
            #pragma unroll
            for (int i = 0; i < 4; i++)
                #pragma unroll
                for (int j = 0; j < 4; j++)
                    acc[i][j] = fmaf(pa[i], va[j], acc[i][j]);
        }
    }

    #pragma unroll
    for (int i = 0; i < 4; i++) {
        const float inv = 1.f / l_i[i];
        float4 o = make_float4(acc[i][0] * inv, acc[i][1] * inv,
                               acc[i][2] * inv, acc[i][3] * inv);
        *(float4*)&y[(size_t)(b * S + qt * 64 + ty * 4 + i) * E + hoff + tx * 4] = o;
    }
}

// ---------------------------------------------------------------------------
extern "C" void kernel_launch(void* const* d_in, const int* in_sizes, int n_in,
                              void* d_out, int out_size)
{
    const float* x      = (const float*)d_in[0];
    const float* w_attn = (const float*)d_in[1];
    const float* w_proj = (const float*)d_in[2];
    float* out = (float*)d_out;

    float* qkv = nullptr;
    float* yb  = nullptr;
    cudaGetSymbolAddress((void**)&qkv, g_qkv);
    cudaGetSymbolAddress((void**)&yb,  g_y);

    // 1) qkv = x @ w_attn   [4096, 3072]  (tf32 mma.sync tensor cores)
    gemm_mma<<<dim3(E3 / 128, BS / 128), 256>>>(x, w_attn, qkv, BS, E3, E);
    // 2) fused causal attention -> y  [4096, 1024]
    attn_kernel<<<dim3(S / 64, B * NHD), 256>>>(qkv, yb);
    // 3) out = y @ w_proj   [4096, 1024]  (tf32 mma.sync tensor cores)
    gemm_mma<<<dim3(E / 128, BS / 128), 256>>>(yb, w_proj, out, BS, E, E);
}

// round 5
// speedup vs baseline: 2.0336x; 1.6303x over previous
#include <cuda_runtime.h>
#include <cstdint>

// Shapes fixed by the problem: B=2, S=2048, E=1024, H=16, D=64.
static constexpr int E   = 1024;
static constexpr int NHD = 16;
static constexpr int HD  = 64;
static constexpr int B   = 2;
static constexpr int S   = 2048;
static constexpr int BS  = B * S;      // 4096 tokens
static constexpr int E3  = 3 * E;      // 3072

__device__ float g_qkv[(size_t)BS * E3];
__device__ float g_y[(size_t)BS * E];

// ---------------------------------------------------------------------------
// tf32 helpers (mma.sync is sm_80+ PTX: legal on the harness's compute_103
// target; tcgen05 is NOT — it needs sm_103a which this toolchain won't emit).
// ---------------------------------------------------------------------------
__device__ __forceinline__ uint32_t f2tf32(float f) {
    uint32_t u;
    asm("cvt.rna.tf32.f32 %0, %1;" : "=r"(u) : "f"(f));
    return u;
}

// D = A(16x8, row) @ B(8x8, col) + C, tf32 in / f32 out.
__device__ __forceinline__ void mma_tf32(float* c, uint32_t a0, uint32_t a1,
                                         uint32_t a2, uint32_t a3,
                                         uint32_t b0, uint32_t b1) {
    asm volatile(
        "mma.sync.aligned.m16n8k8.row.col.f32.tf32.tf32.f32 "
        "{%0,%1,%2,%3}, {%4,%5,%6,%7}, {%8,%9}, {%0,%1,%2,%3};"
        : "+f"(c[0]), "+f"(c[1]), "+f"(c[2]), "+f"(c[3])
        : "r"(a0), "r"(a1), "r"(a2), "r"(a3), "r"(b0), "r"(b1));
}

// ---------------------------------------------------------------------------
// Tensor-core tf32 GEMM (unchanged from R4): C[M,N] = A[M,K] @ Bm[K,N].
// ---------------------------------------------------------------------------
__global__ __launch_bounds__(256) void gemm_mma(
    const float* __restrict__ A, const float* __restrict__ Bm,
    float* __restrict__ C, int M, int N, int K)
{
    __shared__ float As[2][128 * 16];
    __shared__ float Bs[2][128 * 16];

    const int tid  = threadIdx.x;
    const int wid  = tid >> 5;
    const int lane = tid & 31;
    const int g    = lane >> 2;
    const int tig  = lane & 3;
    const int m0   = (wid >> 2) * 64;
    const int n0   = (wid & 3) * 32;
    const int brow = blockIdx.y * 128;
    const int bcol = blockIdx.x * 128;

    const int ar = tid >> 1;
    const int aq = (tid & 1) * 2;
    const int bk = tid >> 4;
    const int bn = (tid & 15) * 4;

    float acc[4][4][4];
    #pragma unroll
    for (int mt = 0; mt < 4; mt++)
        #pragma unroll
        for (int nt = 0; nt < 4; nt++)
            #pragma unroll
            for (int i = 0; i < 4; i++) acc[mt][nt][i] = 0.f;

    const int nIter = K >> 4;
    float4 va[2], vb[2];

    {
        va[0] = *(const float4*)&A[(size_t)(brow + ar) * K + aq * 4];
        va[1] = *(const float4*)&A[(size_t)(brow + ar) * K + aq * 4 + 4];
        vb[0] = *(const float4*)&Bm[(size_t)bk * N + bcol + bn];
        vb[1] = *(const float4*)&Bm[(size_t)bk * N + bcol + bn + 64];
        #pragma unroll
        for (int h = 0; h < 2; h++) {
            const int q = aq + h;
            const float v[4] = {va[h].x, va[h].y, va[h].z, va[h].w};
            #pragma unroll
            for (int i = 0; i < 4; i++)
                *(uint32_t*)&As[0][ar * 16 + ((i ^ (ar & 3)) << 2) + q] = f2tf32(v[i]);
        }
        #pragma unroll
        for (int h = 0; h < 2; h++) {
            const int nb = bn + h * 64;
            const float v[4] = {vb[h].x, vb[h].y, vb[h].z, vb[h].w};
            #pragma unroll
            for (int i = 0; i < 4; i++) {
                const int n = nb + i;
                *(uint32_t*)&Bs[0][n * 16 + (((bk & 3) ^ i ^ ((n >> 2) & 3)) << 2) + (bk >> 2)]
                    = f2tf32(v[i]);
            }
        }
    }
    __syncthreads();

    for (int it = 0; it < nIter; ++it) {
        const int cur = it & 1;
        const bool more = (it + 1) < nIter;
        if (more) {
            const int k0 = (it + 1) << 4;
            va[0] = *(const float4*)&A[(size_t)(brow + ar) * K + k0 + aq * 4];
            va[1] = *(const float4*)&A[(size_t)(brow + ar) * K + k0 + aq * 4 + 4];
            vb[0] = *(const float4*)&Bm[(size_t)(k0 + bk) * N + bcol + bn];
            vb[1] = *(const float4*)&Bm[(size_t)(k0 + bk) * N + bcol + bn + 64];
        }

        float4 bF[4];
        #pragma unroll
        for (int nt = 0; nt < 4; nt++) {
            const int n = n0 + nt * 8 + g;
            bF[nt] = *(const float4*)&Bs[cur][n * 16 + ((tig ^ (n & 3) ^ ((n >> 2) & 3)) << 2)];
        }

        #pragma unroll
        for (int mt = 0; mt < 4; mt++) {
            const int ma = m0 + mt * 16 + g;
            const int mb = ma + 8;
            float4 aR0 = *(const float4*)&As[cur][ma * 16 + ((tig ^ (ma & 3)) << 2)];
            float4 aR1 = *(const float4*)&As[cur][mb * 16 + ((tig ^ (mb & 3)) << 2)];
            #pragma unroll
            for (int nt = 0; nt < 4; nt++)
                mma_tf32(acc[mt][nt],
                         __float_as_uint(aR0.x), __float_as_uint(aR1.x),
                         __float_as_uint(aR0.y), __float_as_uint(aR1.y),
                         __float_as_uint(bF[nt].x), __float_as_uint(bF[nt].y));
            #pragma unroll
            for (int nt = 0; nt < 4; nt++)
                mma_tf32(acc[mt][nt],
                         __float_as_uint(aR0.z), __float_as_uint(aR1.z),
                         __float_as_uint(aR0.w), __float_as_uint(aR1.w),
                         __float_as_uint(bF[nt].z), __float_as_uint(bF[nt].w));
        }

        if (more) {
            const int nxt = cur ^ 1;
            #pragma unroll
            for (int h = 0; h < 2; h++) {
                const int q = aq + h;
                const float v[4] = {va[h].x, va[h].y, va[h].z, va[h].w};
                #pragma unroll
                for (int i = 0; i < 4; i++)
                    *(uint32_t*)&As[nxt][ar * 16 + ((i ^ (ar & 3)) << 2) + q] = f2tf32(v[i]);
            }
            #pragma unroll
            for (int h = 0; h < 2; h++) {
                const int nb = bn + h * 64;
                const float v[4] = {vb[h].x, vb[h].y, vb[h].z, vb[h].w};
                #pragma unroll
                for (int i = 0; i < 4; i++) {
                    const int n = nb + i;
                    *(uint32_t*)&Bs[nxt][n * 16 + (((bk & 3) ^ i ^ ((n >> 2) & 3)) << 2) + (bk >> 2)]
                        = f2tf32(v[i]);
                }
            }
        }
        __syncthreads();
    }

    #pragma unroll
    for (int mt = 0; mt < 4; mt++) {
        #pragma unroll
        for (int nt = 0; nt < 4; nt++) {
            const int r0 = brow + m0 + mt * 16 + g;
            const int cc = bcol + n0 + nt * 8 + 2 * tig;
            *(float2*)&C[(size_t)r0 * N + cc] =
                make_float2(acc[mt][nt][0], acc[mt][nt][1]);
            *(float2*)&C[(size_t)(r0 + 8) * N + cc] =
                make_float2(acc[mt][nt][2], acc[mt][nt][3]);
        }
    }
}

// ---------------------------------------------------------------------------
// Tensor-core flash attention.
// Block = one (b, h, 128-query tile). 256 threads = 8 warps, 16 q-rows/warp.
// Key loop over 64-key tiles. Q fragments live in registers; K/V staged in
// smem (tf32-converted); P round-trips via warp-private smem rows.
// Smem rows padded to 72 floats => all fragment LDS patterns conflict-free.
// ---------------------------------------------------------------------------
static constexpr int ATT_Q_FLOATS = 128 * 72;             // Qs, reused as Ps
static constexpr int ATT_K_FLOATS = 64 * 72;
static constexpr int ATT_SMEM_BYTES =
    (ATT_Q_FLOATS + 2 * ATT_K_FLOATS) * 4;                // 73,728 B

__global__ __launch_bounds__(256) void attn_mma(
    const float* __restrict__ qkv, float* __restrict__ y)
{
    extern __shared__ float sm[];
    float* Qs = sm;                        // [128][72] (later reused as Ps)
    float* Ks = sm + ATT_Q_FLOATS;         // [64][72]
    float* Vs = Ks + ATT_K_FLOATS;         // [64][72]
    float* Ps = Qs;

    const int qt  = blockIdx.x;            // 0..15
    const int bh  = blockIdx.y;            // 0..31
    const int b   = bh >> 4;
    const int h   = bh & 15;
    const int q0  = qt * 128;
    const int tid = threadIdx.x;
    const int wid = tid >> 5;
    const int lane = tid & 31;
    const int g   = lane >> 2;
    const int tig = lane & 3;
    const int w16 = wid * 16;

    const float* base = qkv + (size_t)b * S * E3;
    const int hoff = h * HD;

    // Stage Q (scale folded, tf32-converted), plain [row][72] layout.
    #pragma unroll
    for (int rep = 0; rep < 8; rep++) {
        const int idx = rep * 256 + tid;
        const int r = idx >> 4, d4 = (idx & 15) << 2;
        float4 v = *(const float4*)&base[(size_t)(q0 + r) * E3 + hoff + d4];
        float4 t = make_float4(__uint_as_float(f2tf32(v.x * 0.125f)),
                               __uint_as_float(f2tf32(v.y * 0.125f)),
                               __uint_as_float(f2tf32(v.z * 0.125f)),
                               __uint_as_float(f2tf32(v.w * 0.125f)));
        *(float4*)&Qs[r * 72 + d4] = t;
    }
    __syncthreads();

    // Extract this warp's Q fragments (rows w16+g, w16+g+8; 8 k-steps of d).
    uint32_t qa[8][4];
    #pragma unroll
    for (int kk = 0; kk < 8; kk++) {
        qa[kk][0] = __float_as_uint(Qs[(w16 + g)     * 72 + kk * 8 + tig]);
        qa[kk][1] = __float_as_uint(Qs[(w16 + g + 8) * 72 + kk * 8 + tig]);
        qa[kk][2] = __float_as_uint(Qs[(w16 + g)     * 72 + kk * 8 + tig + 4]);
        qa[kk][3] = __float_as_uint(Qs[(w16 + g + 8) * 72 + kk * 8 + tig + 4]);
    }
    __syncthreads();   // Qs now reusable as Ps

    float o[8][4];
    #pragma unroll
    for (int nt = 0; nt < 8; nt++)
        #pragma unroll
        for (int i = 0; i < 4; i++) o[nt][i] = 0.f;
    float m0v = -1e30f, m1v = -1e30f, l0 = 0.f, l1 = 0.f;

    const int row0g = q0 + w16 + g;        // global row of c0/c1
    const int nkt = 2 * qt + 2;

    for (int kt = 0; kt < nkt; kt++) {
        const int kbase = kt * 64;
        __syncthreads();                   // prior tile's Vs/Ks reads done
        // Stage K and V tiles (tf32).
        #pragma unroll
        for (int rep = 0; rep < 4; rep++) {
            const int idx = rep * 256 + tid;
            const int r = idx >> 4, d4 = (idx & 15) << 2;
            const float* src = &base[(size_t)(kbase + r) * E3 + E + hoff + d4];
            float4 kv = *(const float4*)src;
            float4 vv = *(const float4*)(src + E);
            *(float4*)&Ks[r * 72 + d4] = make_float4(
                __uint_as_float(f2tf32(kv.x)), __uint_as_float(f2tf32(kv.y)),
                __uint_as_float(f2tf32(kv.z)), __uint_as_float(f2tf32(kv.w)));
            *(float4*)&Vs[r * 72 + d4] = make_float4(
                __uint_as_float(f2tf32(vv.x)), __uint_as_float(f2tf32(vv.y)),
                __uint_as_float(f2tf32(vv.z)), __uint_as_float(f2tf32(vv.w)));
        }
        __syncthreads();

        // S = Q @ K^T  (n = keys, k = d)
        float s[8][4];
        #pragma unroll
        for (int nt = 0; nt < 8; nt++)
            #pragma unroll
            for (int i = 0; i < 4; i++) s[nt][i] = 0.f;

        #pragma unroll
        for (int kk = 0; kk < 8; kk++) {
            #pragma unroll
            for (int nt = 0; nt < 8; nt++) {
                const uint32_t b0 =
                    __float_as_uint(Ks[(nt * 8 + g) * 72 + kk * 8 + tig]);
                const uint32_t b1 =
                    __float_as_uint(Ks[(nt * 8 + g) * 72 + kk * 8 + tig + 4]);
                mma_tf32(s[nt], qa[kk][0], qa[kk][1], qa[kk][2], qa[kk][3], b0, b1);
            }
        }

        // Causal mask (only the two diagonal-region tiles need it).
        if (kt >= 2 * qt) {
            #pragma unroll
            for (int nt = 0; nt < 8; nt++) {
                const int key = kbase + nt * 8 + 2 * tig;
                if (key     > row0g)     s[nt][0] = -1e30f;
                if (key + 1 > row0g)     s[nt][1] = -1e30f;
                if (key     > row0g + 8) s[nt][2] = -1e30f;
                if (key + 1 > row0g + 8) s[nt][3] = -1e30f;
            }
        }

        // Online softmax (row g: c0,c1 ; row g+8: c2,c3; quad = lanes sharing g).
        float mx0 = -1e30f, mx1 = -1e30f;
        #pragma unroll
        for (int nt = 0; nt < 8; nt++) {
            mx0 = fmaxf(mx0, fmaxf(s[nt][0], s[nt][1]));
            mx1 = fmaxf(mx1, fmaxf(s[nt][2], s[nt][3]));
        }
        #pragma unroll
        for (int off = 1; off <= 2; off <<= 1) {
            mx0 = fmaxf(mx0, __shfl_xor_sync(0xffffffffu, mx0, off));
            mx1 = fmaxf(mx1, __shfl_xor_sync(0xffffffffu, mx1, off));
        }
        const float nm0 = fmaxf(m0v, mx0);
        const float nm1 = fmaxf(m1v, mx1);
        const float al0 = __expf(m0v - nm0);
        const float al1 = __expf(m1v - nm1);
        m0v = nm0; m1v = nm1;
        float rs0 = 0.f, rs1 = 0.f;
        #pragma unroll
        for (int nt = 0; nt < 8; nt++) {
            s[nt][0] = __expf(s[nt][0] - nm0); rs0 += s[nt][0];
            s[nt][1] = __expf(s[nt][1] - nm0); rs0 += s[nt][1];
            s[nt][2] = __expf(s[nt][2] - nm1); rs1 += s[nt][2];
            s[nt][3] = __expf(s[nt][3] - nm1); rs1 += s[nt][3];
        }
        #pragma unroll
        for (int off = 1; off <= 2; off <<= 1) {
            rs0 += __shfl_xor_sync(0xffffffffu, rs0, off);
            rs1 += __shfl_xor_sync(0xffffffffu, rs1, off);
        }
        l0 = l0 * al0 + rs0;
        l1 = l1 * al1 + rs1;
        #pragma unroll
        for (int nt = 0; nt < 8; nt++) {
            o[nt][0] *= al0; o[nt][1] *= al0;
            o[nt][2] *= al1; o[nt][3] *= al1;
        }

        // P -> smem (tf32), warp-private rows; then O += P @ V (n = d, k = keys).
        #pragma unroll
        for (int nt = 0; nt < 8; nt++) {
            *(float2*)&Ps[(w16 + g) * 72 + nt * 8 + 2 * tig] = make_float2(
                __uint_as_float(f2tf32(s[nt][0])), __uint_as_float(f2tf32(s[nt][1])));
            *(float2*)&Ps[(w16 + g + 8) * 72 + nt * 8 + 2 * tig] = make_float2(
                __uint_as_float(f2tf32(s[nt][2])), __uint_as_float(f2tf32(s[nt][3])));
        }
        __syncwarp();

        #pragma unroll
        for (int kk = 0; kk < 8; kk++) {
            const uint32_t pa0 = __float_as_uint(Ps[(w16 + g)     * 72 + kk * 8 + tig]);
            const uint32_t pa1 = __float_as_uint(Ps[(w16 + g + 8) * 72 + kk * 8 + tig]);
            const uint32_t pa2 = __float_as_uint(Ps[(w16 + g)     * 72 + kk * 8 + tig + 4]);
            const uint32_t pa3 = __float_as_uint(Ps[(w16 + g + 8) * 72 + kk * 8 + tig + 4]);
            #pragma unroll
            for (int nt = 0; nt < 8; nt++) {
                const uint32_t b0 =
                    __float_as_uint(Vs[(kk * 8 + tig)     * 72 + nt * 8 + g]);
                const uint32_t b1 =
                    __float_as_uint(Vs[(kk * 8 + tig + 4) * 72 + nt * 8 + g]);
                mma_tf32(o[nt], pa0, pa1, pa2, pa3, b0, b1);
            }
        }
        __syncwarp();   // Ps reads done before next tile's rescale/overwrite
    }

    // Epilogue: normalize and store.
    const float i0 = 1.f / l0;
    const float i1 = 1.f / l1;
    const size_t gr0 = (size_t)(b * S + q0 + w16 + g) * E + hoff;
    const size_t gr1 = gr0 + 8 * E;
    #pragma unroll
    for (int nt = 0; nt < 8; nt++) {
        const int cc = nt * 8 + 2 * tig;
        *(float2*)&y[gr0 + cc] = make_float2(o[nt][0] * i0, o[nt][1] * i0);
        *(float2*)&y[gr1 + cc] = make_float2(o[nt][2] * i1, o[nt][3] * i1);
    }
}

// ---------------------------------------------------------------------------
extern "C" void kernel_launch(void* const* d_in, const int* in_sizes, int n_in,
                              void* d_out, int out_size)
{
    const float* x      = (const float*)d_in[0];
    const float* w_attn = (const float*)d_in[1];
    const float* w_proj = (const float*)d_in[2];
    float* out = (float*)d_out;

    float* qkv = nullptr;
    float* yb  = nullptr;
    cudaGetSymbolAddress((void**)&qkv, g_qkv);
    cudaGetSymbolAddress((void**)&yb,  g_y);

    cudaFuncSetAttribute(attn_mma, cudaFuncAttributeMaxDynamicSharedMemorySize,
                         ATT_SMEM_BYTES);

    // 1) qkv = x @ w_attn   [4096, 3072]
    gemm_mma<<<dim3(E3 / 128, BS / 128), 256>>>(x, w_attn, qkv, BS, E3, E);
    // 2) tensor-core flash attention -> y  [4096, 1024]
    attn_mma<<<dim3(S / 128, B * NHD), 256, ATT_SMEM_BYTES>>>(qkv, yb);
    // 3) out = y @ w_proj   [4096, 1024]
    gemm_mma<<<dim3(E / 128, BS / 128), 256>>>(yb, w_proj, out, BS, E, E);
}

// round 6
// speedup vs baseline: 2.4210x; 1.1905x over previous
#include <cuda_runtime.h>
#include <cstdint>

// Shapes fixed by the problem: B=2, S=2048, E=1024, H=16, D=64.
static constexpr int E   = 1024;
static constexpr int NHD = 16;
static constexpr int HD  = 64;
static constexpr int B   = 2;
static constexpr int S   = 2048;
static constexpr int BS  = B * S;      // 4096 tokens
static constexpr int E3  = 3 * E;      // 3072

__device__ float g_qkv[(size_t)BS * E3];   // 48 MB
__device__ float g_y[(size_t)BS * E];      // 16 MB
__device__ float g_xc[(size_t)BS * E];     // 16 MB  x, tf32-rounded
__device__ float g_wat[(size_t)E3 * E];    // 12 MB  w_attn^T, tf32-rounded
__device__ float g_wpt[(size_t)E * E];     //  4 MB  w_proj^T, tf32-rounded

// ---------------------------------------------------------------------------
// Helpers (mma.sync/cp.async are sm_80+ PTX: legal on compute_103; tcgen05
// is NOT — it needs the sm_103a target which this toolchain won't emit).
// ---------------------------------------------------------------------------
__device__ __forceinline__ uint32_t f2tf32(float f) {
    uint32_t u;
    asm("cvt.rna.tf32.f32 %0, %1;" : "=r"(u) : "f"(f));
    return u;
}
__device__ __forceinline__ float f2tf32f(float f) {
    return __uint_as_float(f2tf32(f));
}
__device__ __forceinline__ uint32_t smem_u32(const void* p) {
    uint32_t a;
    asm("{ .reg .u64 t; cvta.to.shared.u64 t, %1; cvt.u32.u64 %0, t; }"
        : "=r"(a) : "l"(p));
    return a;
}
__device__ __forceinline__ void cp16(uint32_t dst, const void* src) {
    asm volatile("cp.async.ca.shared.global [%0], [%1], 16;"
                 :: "r"(dst), "l"(src));
}
#define CP_COMMIT() asm volatile("cp.async.commit_group;" ::: "memory")
#define CP_WAIT2()  asm volatile("cp.async.wait_group 2;" ::: "memory")

// D = A(16x8, row) @ B(8x8, col) + C, tf32 in / f32 out.
__device__ __forceinline__ void mma_tf32(float* c, uint32_t a0, uint32_t a1,
                                         uint32_t a2, uint32_t a3,
                                         uint32_t b0, uint32_t b1) {
    asm volatile(
        "mma.sync.aligned.m16n8k8.row.col.f32.tf32.tf32.f32 "
        "{%0,%1,%2,%3}, {%4,%5,%6,%7}, {%8,%9}, {%0,%1,%2,%3};"
        : "+f"(c[0]), "+f"(c[1]), "+f"(c[2]), "+f"(c[3])
        : "r"(a0), "r"(a1), "r"(a2), "r"(a3), "r"(b0), "r"(b1));
}

// ---------------------------------------------------------------------------
// Pre-pass kernels.
// ---------------------------------------------------------------------------
__global__ void cvt_tf32_k(const float* __restrict__ in, float* __restrict__ out,
                           int n4) {
    const int i = blockIdx.x * blockDim.x + threadIdx.x;
    if (i < n4) {
        float4 v = ((const float4*)in)[i];
        ((float4*)out)[i] = make_float4(f2tf32f(v.x), f2tf32f(v.y),
                                        f2tf32f(v.z), f2tf32f(v.w));
    }
}

// out[Cc][R] = tf32(in[R][Cc])   (block 32x8, tile 32x32)
__global__ void transpose_cvt_k(const float* __restrict__ in,
                                float* __restrict__ out, int R, int Cc) {
    __shared__ float t[32][33];
    const int c0 = blockIdx.x * 32, r0 = blockIdx.y * 32;
    #pragma unroll
    for (int j = 0; j < 4; j++) {
        const int r = threadIdx.y + j * 8;
        t[r][threadIdx.x] = in[(size_t)(r0 + r) * Cc + c0 + threadIdx.x];
    }
    __syncthreads();
    #pragma unroll
    for (int j = 0; j < 4; j++) {
        const int c = threadIdx.y + j * 8;
        out[(size_t)(c0 + c) * R + r0 + threadIdx.x] = f2tf32f(t[threadIdx.x][c]);
    }
}

// ---------------------------------------------------------------------------
// Tensor-core tf32 GEMM, cp.async pipelined:
//   C[M,N] = At[M,K] @ Bt[N,K]^T   (both operands K-major, tf32-prerounded)
// CTA tile 128x128, BK=16, 256 threads = 8 warps (2m x 4n), warp tile 64x32.
// Smem: 4 stages x (A 128x20f + B 128x20f) = 80 KB; rows padded 16->20 floats
// so all scalar fragment LDS hit 32 distinct banks ((20g+tig)%32 bijective).
// 2 CTAs/SM: one CTA's sync/epilogue overlaps the other's MMA phase.
// ---------------------------------------------------------------------------
static constexpr int GST_FLOATS = 2 * 128 * 20;             // 5120 f = 20 KB
static constexpr int GEMM_SMEM  = 4 * GST_FLOATS * 4;       // 81920 B

__global__ __launch_bounds__(256, 2) void gemm_tc(
    const float* __restrict__ At, const float* __restrict__ Bt,
    float* __restrict__ C, int M, int N, int K)
{
    extern __shared__ float smf[];
    const uint32_t sbase = smem_u32(smf);

    const int tid  = threadIdx.x;
    const int wid  = tid >> 5;
    const int lane = tid & 31;
    const int g    = lane >> 2;
    const int tig  = lane & 3;
    const int m0   = (wid >> 2) * 64;
    const int n0   = (wid & 3) * 32;
    const int brow = blockIdx.y * 128;
    const int bcol = blockIdx.x * 128;

    // cp.async mapping: thread -> (row, 2 of 4 16B-chunks) for A and B tiles.
    const int lr = tid >> 1;
    const int lc = (tid & 1) * 2;
    const float* gA = At + (size_t)(brow + lr) * K + lc * 4;
    const float* gB = Bt + (size_t)(bcol + lr) * K + lc * 4;
    const uint32_t dOffA = (uint32_t)(lr * 80 + lc * 16);

    float acc[4][4][4];
    #pragma unroll
    for (int mt = 0; mt < 4; mt++)
        #pragma unroll
        for (int nt = 0; nt < 4; nt++)
            #pragma unroll
            for (int i = 0; i < 4; i++) acc[mt][nt][i] = 0.f;

    const int nIter = K >> 4;

    #define G_ISSUE(it) do {                                                  \
        const int _st = (it) & 3;                                             \
        const uint32_t _dA = sbase + _st * (GST_FLOATS * 4) + dOffA;          \
        const float* _sa = gA + (it) * 16;                                    \
        const float* _sb = gB + (it) * 16;                                    \
        cp16(_dA,         _sa);                                               \
        cp16(_dA + 16,    _sa + 4);                                           \
        cp16(_dA + 10240, _sb);                                               \
        cp16(_dA + 10256, _sb + 4);                                           \
    } while (0)

    G_ISSUE(0); CP_COMMIT();
    G_ISSUE(1); CP_COMMIT();

    for (int it = 0; it < nIter; ++it) {
        if (it + 2 < nIter) G_ISSUE(it + 2);
        CP_COMMIT();
        CP_WAIT2();
        __syncthreads();

        const float* SA = smf + (it & 3) * GST_FLOATS;
        const float* SB = SA + 2560;

        float bF[4][4];
        #pragma unroll
        for (int nt = 0; nt < 4; nt++) {
            const float* rp = SB + (n0 + nt * 8 + g) * 20;
            bF[nt][0] = rp[tig];     bF[nt][1] = rp[tig + 4];
            bF[nt][2] = rp[tig + 8]; bF[nt][3] = rp[tig + 12];
        }
        #pragma unroll
        for (int mt = 0; mt < 4; mt++) {
            const float* ra = SA + (m0 + mt * 16 + g) * 20;
            const float* rb = ra + 8 * 20;
            const float a00 = ra[tig],      a01 = rb[tig];
            const float a02 = ra[tig + 4],  a03 = rb[tig + 4];
            const float a10 = ra[tig + 8],  a11 = rb[tig + 8];
            const float a12 = ra[tig + 12], a13 = rb[tig + 12];
            #pragma unroll
            for (int nt = 0; nt < 4; nt++)
                mma_tf32(acc[mt][nt],
                         __float_as_uint(a00), __float_as_uint(a01),
                         __float_as_uint(a02), __float_as_uint(a03),
                         __float_as_uint(bF[nt][0]), __float_as_uint(bF[nt][1]));
            #pragma unroll
            for (int nt = 0; nt < 4; nt++)
                mma_tf32(acc[mt][nt],
                         __float_as_uint(a10), __float_as_uint(a11),
                         __float_as_uint(a12), __float_as_uint(a13),
                         __float_as_uint(bF[nt][2]), __float_as_uint(bF[nt][3]));
        }
    }
    #undef G_ISSUE

    // Epilogue: c0,c1 -> (row g, cols 2tig,2tig+1); c2,c3 -> row g+8.
    #pragma unroll
    for (int mt = 0; mt < 4; mt++) {
        #pragma unroll
        for (int nt = 0; nt < 4; nt++) {
            const int r0 = brow + m0 + mt * 16 + g;
            const int cc = bcol + n0 + nt * 8 + 2 * tig;
            *(float2*)&C[(size_t)r0 * N + cc] =
                make_float2(acc[mt][nt][0], acc[mt][nt][1]);
            *(float2*)&C[(size_t)(r0 + 8) * N + cc] =
                make_float2(acc[mt][nt][2], acc[mt][nt][3]);
        }
    }
}

// ---------------------------------------------------------------------------
// Tensor-core flash attention (unchanged from R5).
// Block = one (b, h, 128-query tile). 256 threads = 8 warps, 16 q-rows/warp.
// ---------------------------------------------------------------------------
static constexpr int ATT_Q_FLOATS = 128 * 72;
static constexpr int ATT_K_FLOATS = 64 * 72;
static constexpr int ATT_SMEM_BYTES =
    (ATT_Q_FLOATS + 2 * ATT_K_FLOATS) * 4;                // 73,728 B

__global__ __launch_bounds__(256) void attn_mma(
    const float* __restrict__ qkv, float* __restrict__ y)
{
    extern __shared__ float sm[];
    float* Qs = sm;
    float* Ks = sm + ATT_Q_FLOATS;
    float* Vs = Ks + ATT_K_FLOATS;
    float* Ps = Qs;

    const int qt  = blockIdx.x;
    const int bh  = blockIdx.y;
    const int b   = bh >> 4;
    const int h   = bh & 15;
    const int q0  = qt * 128;
    const int tid = threadIdx.x;
    const int wid = tid >> 5;
    const int lane = tid & 31;
    const int g   = lane >> 2;
    const int tig = lane & 3;
    const int w16 = wid * 16;

    const float* base = qkv + (size_t)b * S * E3;
    const int hoff = h * HD;

    #pragma unroll
    for (int rep = 0; rep < 8; rep++) {
        const int idx = rep * 256 + tid;
        const int r = idx >> 4, d4 = (idx & 15) << 2;
        float4 v = *(const float4*)&base[(size_t)(q0 + r) * E3 + hoff + d4];
        *(float4*)&Qs[r * 72 + d4] = make_float4(
            f2tf32f(v.x * 0.125f), f2tf32f(v.y * 0.125f),
            f2tf32f(v.z * 0.125f), f2tf32f(v.w * 0.125f));
    }
    __syncthreads();

    uint32_t qa[8][4];
    #pragma unroll
    for (int kk = 0; kk < 8; kk++) {
        qa[kk][0] = __float_as_uint(Qs[(w16 + g)     * 72 + kk * 8 + tig]);
        qa[kk][1] = __float_as_uint(Qs[(w16 + g + 8) * 72 + kk * 8 + tig]);
        qa[kk][2] = __float_as_uint(Qs[(w16 + g)     * 72 + kk * 8 + tig + 4]);
        qa[kk][3] = __float_as_uint(Qs[(w16 + g + 8) * 72 + kk * 8 + tig + 4]);
    }
    __syncthreads();

    float o[8][4];
    #pragma unroll
    for (int nt = 0; nt < 8; nt++)
        #pragma unroll
        for (int i = 0; i < 4; i++) o[nt][i] = 0.f;
    float m0v = -1e30f, m1v = -1e30f, l0 = 0.f, l1 = 0.f;

    const int row0g = q0 + w16 + g;
    const int nkt = 2 * qt + 2;

    for (int kt = 0; kt < nkt; kt++) {
        const int kbase = kt * 64;
        __syncthreads();
        #pragma unroll
        for (int rep = 0; rep < 4; rep++) {
            const int idx = rep * 256 + tid;
            const int r = idx >> 4, d4 = (idx & 15) << 2;
            const float* src = &base[(size_t)(kbase + r) * E3 + E + hoff + d4];
            float4 kv = *(const float4*)src;
            float4 vv = *(const float4*)(src + E);
            *(float4*)&Ks[r * 72 + d4] = make_float4(
                f2tf32f(kv.x), f2tf32f(kv.y), f2tf32f(kv.z), f2tf32f(kv.w));
            *(float4*)&Vs[r * 72 + d4] = make_float4(
                f2tf32f(vv.x), f2tf32f(vv.y), f2tf32f(vv.z), f2tf32f(vv.w));
        }
        __syncthreads();

        float s[8][4];
        #pragma unroll
        for (int nt = 0; nt < 8; nt++)
            #pragma unroll
            for (int i = 0; i < 4; i++) s[nt][i] = 0.f;

        #pragma unroll
        for (int kk = 0; kk < 8; kk++) {
            #pragma unroll
            for (int nt = 0; nt < 8; nt++) {
                const uint32_t b0 =
                    __float_as_uint(Ks[(nt * 8 + g) * 72 + kk * 8 + tig]);
                const uint32_t b1 =
                    __float_as_uint(Ks[(nt * 8 + g) * 72 + kk * 8 + tig + 4]);
                mma_tf32(s[nt], qa[kk][0], qa[kk][1], qa[kk][2], qa[kk][3], b0, b1);
            }
        }

        if (kt >= 2 * qt) {
            #pragma unroll
            for (int nt = 0; nt < 8; nt++) {
                const int key = kbase + nt * 8 + 2 * tig;
                if (key     > row0g)     s[nt][0] = -1e30f;
                if (key + 1 > row0g)     s[nt][1] = -1e30f;
                if (key     > row0g + 8) s[nt][2] = -1e30f;
                if (key + 1 > row0g + 8) s[nt][3] = -1e30f;
            }
        }

        float mx0 = -1e30f, mx1 = -1e30f;
        #pragma unroll
        for (int nt = 0; nt < 8; nt++) {
            mx0 = fmaxf(mx0, fmaxf(s[nt][0], s[nt][1]));
            mx1 = fmaxf(mx1, fmaxf(s[nt][2], s[nt][3]));
        }
        #pragma unroll
        for (int off = 1; off <= 2; off <<= 1) {
            mx0 = fmaxf(mx0, __shfl_xor_sync(0xffffffffu, mx0, off));
            mx1 = fmaxf(mx1, __shfl_xor_sync(0xffffffffu, mx1, off));
        }
        const float nm0 = fmaxf(m0v, mx0);
        const float nm1 = fmaxf(m1v, mx1);
        const float al0 = __expf(m0v - nm0);
        const float al1 = __expf(m1v - nm1);
        m0v = nm0; m1v = nm1;
        float rs0 = 0.f, rs1 = 0.f;
        #pragma unroll
        for (int nt = 0; nt < 8; nt++) {
            s[nt][0] = __expf(s[nt][0] - nm0); rs0 += s[nt][0];
            s[nt][1] = __expf(s[nt][1] - nm0); rs0 += s[nt][1];
            s[nt][2] = __expf(s[nt][2] - nm1); rs1 += s[nt][2];
            s[nt][3] = __expf(s[nt][3] - nm1); rs1 += s[nt][3];
        }
        #pragma unroll
        for (int off = 1; off <= 2; off <<= 1) {
            rs0 += __shfl_xor_sync(0xffffffffu, rs0, off);
            rs1 += __shfl_xor_sync(0xffffffffu, rs1, off);
        }
        l0 = l0 * al0 + rs0;
        l1 = l1 * al1 + rs1;
        #pragma unroll
        for (int nt = 0; nt < 8; nt++) {
            o[nt][0] *= al0; o[nt][1] *= al0;
            o[nt][2] *= al1; o[nt][3] *= al1;
        }

        #pragma unroll
        for (int nt = 0; nt < 8; nt++) {
            *(float2*)&Ps[(w16 + g) * 72 + nt * 8 + 2 * tig] = make_float2(
                f2tf32f(s[nt][0]), f2tf32f(s[nt][1]));
            *(float2*)&Ps[(w16 + g + 8) * 72 + nt * 8 + 2 * tig] = make_float2(
                f2tf32f(s[nt][2]), f2tf32f(s[nt][3]));
        }
        __syncwarp();

        #pragma unroll
        for (int kk = 0; kk < 8; kk++) {
            const uint32_t pa0 = __float_as_uint(Ps[(w16 + g)     * 72 + kk * 8 + tig]);
            const uint32_t pa1 = __float_as_uint(Ps[(w16 + g + 8) * 72 + kk * 8 + tig]);
            const uint32_t pa2 = __float_as_uint(Ps[(w16 + g)     * 72 + kk * 8 + tig + 4]);
            const uint32_t pa3 = __float_as_uint(Ps[(w16 + g + 8) * 72 + kk * 8 + tig + 4]);
            #pragma unroll
            for (int nt = 0; nt < 8; nt++) {
                const uint32_t b0 =
                    __float_as_uint(Vs[(kk * 8 + tig)     * 72 + nt * 8 + g]);
                const uint32_t b1 =
                    __float_as_uint(Vs[(kk * 8 + tig + 4) * 72 + nt * 8 + g]);
                mma_tf32(o[nt], pa0, pa1, pa2, pa3, b0, b1);
            }
        }
        __syncwarp();
    }

    const float i0 = 1.f / l0;
    const float i1 = 1.f / l1;
    const size_t gr0 = (size_t)(b * S + q0 + w16 + g) * E + hoff;
    const size_t gr1 = gr0 + 8 * E;
    #pragma unroll
    for (int nt = 0; nt < 8; nt++) {
        const int cc = nt * 8 + 2 * tig;
        *(float2*)&y[gr0 + cc] = make_float2(o[nt][0] * i0, o[nt][1] * i0);
        *(float2*)&y[gr1 + cc] = make_float2(o[nt][2] * i1, o[nt][3] * i1);
    }
}

// ---------------------------------------------------------------------------
extern "C" void kernel_launch(void* const* d_in, const int* in_sizes, int n_in,
                              void* d_out, int out_size)
{
    const float* x      = (const float*)d_in[0];
    const float* w_attn = (const float*)d_in[1];
    const float* w_proj = (const float*)d_in[2];
    float* out = (float*)d_out;

    float *qkv, *yb, *xc, *wat, *wpt;
    cudaGetSymbolAddress((void**)&qkv, g_qkv);
    cudaGetSymbolAddress((void**)&yb,  g_y);
    cudaGetSymbolAddress((void**)&xc,  g_xc);
    cudaGetSymbolAddress((void**)&wat, g_wat);
    cudaGetSymbolAddress((void**)&wpt, g_wpt);

    cudaFuncSetAttribute(gemm_tc, cudaFuncAttributeMaxDynamicSharedMemorySize,
                         GEMM_SMEM);
    cudaFuncSetAttribute(attn_mma, cudaFuncAttributeMaxDynamicSharedMemorySize,
                         ATT_SMEM_BYTES);

    // Pre-passes: tf32-round x; transpose+round weights.
    cvt_tf32_k<<<(BS * E / 4 + 255) / 256, 256>>>(x, xc, BS * E / 4);
    transpose_cvt_k<<<dim3(E3 / 32, E / 32), dim3(32, 8)>>>(w_attn, wat, E, E3);
    transpose_cvt_k<<<dim3(E / 32, E / 32), dim3(32, 8)>>>(w_proj, wpt, E, E);

    // 1) qkv = x @ w_attn   [4096, 3072]
    gemm_tc<<<dim3(E3 / 128, BS / 128), 256, GEMM_SMEM>>>(xc, wat, qkv, BS, E3, E);
    // 2) tensor-core flash attention -> y  [4096, 1024]
    attn_mma<<<dim3(S / 128, B * NHD), 256, ATT_SMEM_BYTES>>>(qkv, yb);
    // 3) out = y @ w_proj   [4096, 1024]
    cvt_tf32_k<<<(BS * E / 4 + 255) / 256, 256>>>(yb, yb, BS * E / 4);
    gemm_tc<<<dim3(E / 128, BS / 128), 256, GEMM_SMEM>>>(yb, wpt, out, BS, E, E);
}

// round 8
// speedup vs baseline: 2.7222x; 1.1244x over previous
#include <cuda_runtime.h>
#include <cstdint>

// Shapes fixed by the problem: B=2, S=2048, E=1024, H=16, D=64.
static constexpr int E   = 1024;
static constexpr int NHD = 16;
static constexpr int HD  = 64;
static constexpr int B   = 2;
static constexpr int S   = 2048;
static constexpr int BS  = B * S;      // 4096 tokens
static constexpr int E3  = 3 * E;      // 3072

__device__ float g_qkv[(size_t)BS * E3];   // 48 MB
__device__ float g_y[(size_t)BS * E];      // 16 MB
__device__ float g_xc[(size_t)BS * E];     // 16 MB  permuted x / permuted y
__device__ float g_wat[(size_t)E3 * E];    // 12 MB  w_attn^T, permuted
__device__ float g_wpt[(size_t)E * E];     //  4 MB  w_proj^T, permuted

// ---------------------------------------------------------------------------
// Helpers (mma.sync/cp.async are sm_80+ PTX: legal on compute_103; tcgen05
// is NOT — it needs the sm_103a target which this toolchain won't emit).
//
// Permuted operand layout ("quadset" layout), per row of K floats, per
// 16-float k-group: chunk c (16B) holds quadset q = c ^ (row&3), i.e. elements
// k = q, q+4, q+8, q+12 (components j=0..3). A lane's m16n8k8 fragment for
// 2 k-steps is then exactly one 16B chunk -> LDS.128, conflict-free.
// ---------------------------------------------------------------------------
__device__ __forceinline__ uint32_t f2tf32(float f) {
    uint32_t u;
    asm("cvt.rna.tf32.f32 %0, %1;" : "=r"(u) : "f"(f));
    return u;
}
__device__ __forceinline__ float f2tf32f(float f) {
    return __uint_as_float(f2tf32(f));
}
__device__ __forceinline__ uint32_t smem_u32(const void* p) {
    uint32_t a;
    asm("{ .reg .u64 t; cvta.to.shared.u64 t, %1; cvt.u32.u64 %0, t; }"
        : "=r"(a) : "l"(p));
    return a;
}
__device__ __forceinline__ void cp16(uint32_t dst, const void* src) {
    asm volatile("cp.async.ca.shared.global [%0], [%1], 16;"
                 :: "r"(dst), "l"(src));
}
#define CP_COMMIT() asm volatile("cp.async.commit_group;" ::: "memory")
#define CP_WAIT2()  asm volatile("cp.async.wait_group 2;" ::: "memory")

// D = A(16x8, row) @ B(8x8, col) + C, tf32 in / f32 out.
__device__ __forceinline__ void mma_tf32(float* c, uint32_t a0, uint32_t a1,
                                         uint32_t a2, uint32_t a3,
                                         uint32_t b0, uint32_t b1) {
    asm volatile(
        "mma.sync.aligned.m16n8k8.row.col.f32.tf32.tf32.f32 "
        "{%0,%1,%2,%3}, {%4,%5,%6,%7}, {%8,%9}, {%0,%1,%2,%3};"
        : "+f"(c[0]), "+f"(c[1]), "+f"(c[2]), "+f"(c[3])
        : "r"(a0), "r"(a1), "r"(a2), "r"(a3), "r"(b0), "r"(b1));
}

// ---------------------------------------------------------------------------
// Pre-pass kernels.
// ---------------------------------------------------------------------------
// Row-preserving cvt+permute: out[r][group, chunk c, j] = tf32(in[r][group + (c^(r&3)) + 4j]).
// One thread per 16B output chunk. Kf = row length (multiple of 16).
__global__ void permute_cvt_k(const float* __restrict__ in,
                              float* __restrict__ out, int nChunks, int Kf) {
    const int idx = blockIdx.x * blockDim.x + threadIdx.x;
    if (idx >= nChunks) return;
    const int cpr = Kf >> 2;                 // chunks per row
    const int r = idx / cpr;
    const int pos = idx - r * cpr;           // chunk within row
    const int gbase = (pos >> 2) << 4;       // k-group base
    const int c = pos & 3;
    const int q = c ^ (r & 3);
    const float* src = in + (size_t)r * Kf + gbase + q;
    ((float4*)out)[idx] = make_float4(f2tf32f(src[0]), f2tf32f(src[4]),
                                      f2tf32f(src[8]), f2tf32f(src[12]));
}

// Transpose + cvt + permute: logical out[n][k] = tf32(in[k][n]), stored in
// quadset layout. in: [R][Cc] (R = k-dim, Cc = n-dim). Block 32x8, tile 32x32.
__global__ void transpose_permute_k(const float* __restrict__ in,
                                    float* __restrict__ out, int R, int Cc) {
    __shared__ float t[32][33];
    const int c0 = blockIdx.x * 32, r0 = blockIdx.y * 32;
    #pragma unroll
    for (int j = 0; j < 4; j++) {
        const int r = threadIdx.y + j * 8;
        t[r][threadIdx.x] = in[(size_t)(r0 + r) * Cc + c0 + threadIdx.x];
    }
    __syncthreads();
    const int x = threadIdx.x;               // output k position within 32
    #pragma unroll
    for (int j = 0; j < 4; j++) {
        const int nl = threadIdx.y + j * 8;  // local n
        const int src_kk = (x & 16) | ((((x >> 2) & 3) ^ (nl & 3)) + ((x & 3) << 2));
        out[(size_t)(c0 + nl) * R + r0 + x] = f2tf32f(t[src_kk][nl]);
    }
}

// ---------------------------------------------------------------------------
// Tensor-core tf32 GEMM, cp.async pipelined, quadset-permuted operands:
//   C[M,N] = At[M,K] @ Bt[N,K]^T   (both K-major, tf32-prerounded, permuted)
// CTA tile 128x128, BK=16, 256 threads = 8 warps (2m x 4n), warp tile 64x32.
// Smem: 4 stages x (A 128x16f + B 128x16f) = 64 KB, rows exactly 64B.
// All fragment loads are single LDS.128, conflict-free. 2 CTAs/SM.
// ---------------------------------------------------------------------------
static constexpr int GST_FLOATS = 2 * 128 * 16;             // 4096 f = 16 KB
static constexpr int GEMM_SMEM  = 4 * GST_FLOATS * 4;       // 65536 B

__global__ __launch_bounds__(256, 2) void gemm_tc(
    const float* __restrict__ At, const float* __restrict__ Bt,
    float* __restrict__ C, int M, int N, int K)
{
    extern __shared__ float smf[];
    const uint32_t sbase = smem_u32(smf);

    const int tid  = threadIdx.x;
    const int wid  = tid >> 5;
    const int lane = tid & 31;
    const int g    = lane >> 2;
    const int tig  = lane & 3;
    const int m0   = (wid >> 2) * 64;
    const int n0   = (wid & 3) * 32;
    const int brow = blockIdx.y * 128;
    const int bcol = blockIdx.x * 128;

    // cp.async mapping: thread -> (row, 2 consecutive 16B chunks), A and B.
    const int lr = tid >> 1;
    const int lc = (tid & 1) * 2;
    const float* gA = At + (size_t)(brow + lr) * K + lc * 4;
    const float* gB = Bt + (size_t)(bcol + lr) * K + lc * 4;
    const uint32_t dOff = (uint32_t)(lr * 64 + lc * 16);

    float acc[4][4][4];
    #pragma unroll
    for (int mt = 0; mt < 4; mt++)
        #pragma unroll
        for (int nt = 0; nt < 4; nt++)
            #pragma unroll
            for (int i = 0; i < 4; i++) acc[mt][nt][i] = 0.f;

    const int nIter = K >> 4;

    #define G_ISSUE(it) do {                                                  \
        const uint32_t _dA = sbase + ((it) & 3) * (GST_FLOATS * 4) + dOff;    \
        const float* _sa = gA + (it) * 16;                                    \
        const float* _sb = gB + (it) * 16;                                    \
        cp16(_dA,        _sa);                                                \
        cp16(_dA + 16,   _sa + 4);                                            \
        cp16(_dA + 8192, _sb);                                                \
        cp16(_dA + 8208, _sb + 4);                                            \
    } while (0)

    G_ISSUE(0); CP_COMMIT();
    G_ISSUE(1); CP_COMMIT();

    for (int it = 0; it < nIter; ++it) {
        if (it + 2 < nIter) G_ISSUE(it + 2);
        CP_COMMIT();
        CP_WAIT2();
        __syncthreads();

        const float* SA = smf + (it & 3) * GST_FLOATS;
        const float* SB = SA + 2048;

        // B fragments: one LDS.128 per n-tile (covers both k-steps).
        float4 bF[4];
        #pragma unroll
        for (int nt = 0; nt < 4; nt++) {
            const int n = n0 + nt * 8 + g;
            bF[nt] = *(const float4*)&SB[n * 16 + ((tig ^ (n & 3)) << 2)];
        }
        #pragma unroll
        for (int mt = 0; mt < 4; mt++) {
            const int ma = m0 + mt * 16 + g;
            const float4 a0v = *(const float4*)&SA[ma * 16 + ((tig ^ (ma & 3)) << 2)];
            const float4 a1v = *(const float4*)&SA[(ma + 8) * 16 + ((tig ^ (ma & 3)) << 2)];
            #pragma unroll
            for (int nt = 0; nt < 4; nt++)
                mma_tf32(acc[mt][nt],
                         __float_as_uint(a0v.x), __float_as_uint(a1v.x),
                         __float_as_uint(a0v.y), __float_as_uint(a1v.y),
                         __float_as_uint(bF[nt].x), __float_as_uint(bF[nt].y));
            #pragma unroll
            for (int nt = 0; nt < 4; nt++)
                mma_tf32(acc[mt][nt],
                         __float_as_uint(a0v.z), __float_as_uint(a1v.z),
                         __float_as_uint(a0v.w), __float_as_uint(a1v.w),
                         __float_as_uint(bF[nt].z), __float_as_uint(bF[nt].w));
        }
    }
    #undef G_ISSUE

    // Epilogue: c0,c1 -> (row g, cols 2tig,2tig+1); c2,c3 -> row g+8.
    #pragma unroll
    for (int mt = 0; mt < 4; mt++) {
        #pragma unroll
        for (int nt = 0; nt < 4; nt++) {
            const int r0 = brow + m0 + mt * 16 + g;
            const int cc = bcol + n0 + nt * 8 + 2 * tig;
            *(float2*)&C[(size_t)r0 * N + cc] =
                make_float2(acc[mt][nt][0], acc[mt][nt][1]);
            *(float2*)&C[(size_t)(r0 + 8) * N + cc] =
                make_float2(acc[mt][nt][2], acc[mt][nt][3]);
        }
    }
}

// ---------------------------------------------------------------------------
// Tensor-core flash attention (unchanged from R6).
// ---------------------------------------------------------------------------
static constexpr int ATT_Q_FLOATS = 128 * 72;
static constexpr int ATT_K_FLOATS = 64 * 72;
static constexpr int ATT_SMEM_BYTES =
    (ATT_Q_FLOATS + 2 * ATT_K_FLOATS) * 4;                // 73,728 B

__global__ __launch_bounds__(256) void attn_mma(
    const float* __restrict__ qkv, float* __restrict__ y)
{
    extern __shared__ float sm[];
    float* Qs = sm;
    float* Ks = sm + ATT_Q_FLOATS;
    float* Vs = Ks + ATT_K_FLOATS;
    float* Ps = Qs;

    const int qt  = blockIdx.x;
    const int bh  = blockIdx.y;
    const int b   = bh >> 4;
    const int h   = bh & 15;
    const int q0  = qt * 128;
    const int tid = threadIdx.x;
    const int wid = tid >> 5;
    const int lane = tid & 31;
    const int g   = lane >> 2;
    const int tig = lane & 3;
    const int w16 = wid * 16;

    const float* base = qkv + (size_t)b * S * E3;
    const int hoff = h * HD;

    #pragma unroll
    for (int rep = 0; rep < 8; rep++) {
        const int idx = rep * 256 + tid;
        const int r = idx >> 4, d4 = (idx & 15) << 2;
        float4 v = *(const float4*)&base[(size_t)(q0 + r) * E3 + hoff + d4];
        *(float4*)&Qs[r * 72 + d4] = make_float4(
            f2tf32f(v.x * 0.125f), f2tf32f(v.y * 0.125f),
            f2tf32f(v.z * 0.125f), f2tf32f(v.w * 0.125f));
    }
    __syncthreads();

    uint32_t qa[8][4];
    #pragma unroll
    for (int kk = 0; kk < 8; kk++) {
        qa[kk][0] = __float_as_uint(Qs[(w16 + g)     * 72 + kk * 8 + tig]);
        qa[kk][1] = __float_as_uint(Qs[(w16 + g + 8) * 72 + kk * 8 + tig]);
        qa[kk][2] = __float_as_uint(Qs[(w16 + g)     * 72 + kk * 8 + tig + 4]);
        qa[kk][3] = __float_as_uint(Qs[(w16 + g + 8) * 72 + kk * 8 + tig + 4]);
    }
    __syncthreads();

    float o[8][4];
    #pragma unroll
    for (int nt = 0; nt < 8; nt++)
        #pragma unroll
        for (int i = 0; i < 4; i++) o[nt][i] = 0.f;
    float m0v = -1e30f, m1v = -1e30f, l0 = 0.f, l1 = 0.f;

    const int row0g = q0 + w16 + g;
    const int nkt = 2 * qt + 2;

    for (int kt = 0; kt < nkt; kt++) {
        const int kbase = kt * 64;
        __syncthreads();
        #pragma unroll
        for (int rep = 0; rep < 4; rep++) {
            const int idx = rep * 256 + tid;
            const int r = idx >> 4, d4 = (idx & 15) << 2;
            const float* src = &base[(size_t)(kbase + r) * E3 + E + hoff + d4];
            float4 kv = *(const float4*)src;
            float4 vv = *(const float4*)(src + E);
            *(float4*)&Ks[r * 72 + d4] = make_float4(
                f2tf32f(kv.x), f2tf32f(kv.y), f2tf32f(kv.z), f2tf32f(kv.w));
            *(float4*)&Vs[r * 72 + d4] = make_float4(
                f2tf32f(vv.x), f2tf32f(vv.y), f2tf32f(vv.z), f2tf32f(vv.w));
        }
        __syncthreads();

        float s[8][4];
        #pragma unroll
        for (int nt = 0; nt < 8; nt++)
            #pragma unroll
            for (int i = 0; i < 4; i++) s[nt][i] = 0.f;

        #pragma unroll
        for (int kk = 0; kk < 8; kk++) {
            #pragma unroll
            for (int nt = 0; nt < 8; nt++) {
                const uint32_t b0 =
                    __float_as_uint(Ks[(nt * 8 + g) * 72 + kk * 8 + tig]);
                const uint32_t b1 =
                    __float_as_uint(Ks[(nt * 8 + g) * 72 + kk * 8 + tig + 4]);
                mma_tf32(s[nt], qa[kk][0], qa[kk][1], qa[kk][2], qa[kk][3], b0, b1);
            }
        }

        if (kt >= 2 * qt) {
            #pragma unroll
            for (int nt = 0; nt < 8; nt++) {
                const int key = kbase + nt * 8 + 2 * tig;
                if (key     > row0g)     s[nt][0] = -1e30f;
                if (key + 1 > row0g)     s[nt][1] = -1e30f;
                if (key     > row0g + 8) s[nt][2] = -1e30f;
                if (key + 1 > row0g + 8) s[nt][3] = -1e30f;
            }
        }

        float mx0 = -1e30f, mx1 = -1e30f;
        #pragma unroll
        for (int nt = 0; nt < 8; nt++) {
            mx0 = fmaxf(mx0, fmaxf(s[nt][0], s[nt][1]));
            mx1 = fmaxf(mx1, fmaxf(s[nt][2], s[nt][3]));
        }
        #pragma unroll
        for (int off = 1; off <= 2; off <<= 1) {
            mx0 = fmaxf(mx0, __shfl_xor_sync(0xffffffffu, mx0, off));
            mx1 = fmaxf(mx1, __shfl_xor_sync(0xffffffffu, mx1, off));
        }
        const float nm0 = fmaxf(m0v, mx0);
        const float nm1 = fmaxf(m1v, mx1);
        const float al0 = __expf(m0v - nm0);
        const float al1 = __expf(m1v - nm1);
        m0v = nm0; m1v = nm1;
        float rs0 = 0.f, rs1 = 0.f;
        #pragma unroll
        for (int nt = 0; nt < 8; nt++) {
            s[nt][0] = __expf(s[nt][0] - nm0); rs0 += s[nt][0];
            s[nt][1] = __expf(s[nt][1] - nm0); rs0 += s[nt][1];
            s[nt][2] = __expf(s[nt][2] - nm1); rs1 += s[nt][2];
            s[nt][3] = __expf(s[nt][3] - nm1); rs1 += s[nt][3];
        }
        #pragma unroll
        for (int off = 1; off <= 2; off <<= 1) {
            rs0 += __shfl_xor_sync(0xffffffffu, rs0, off);
            rs1 += __shfl_xor_sync(0xffffffffu, rs1, off);
        }
        l0 = l0 * al0 + rs0;
        l1 = l1 * al1 + rs1;
        #pragma unroll
        for (int nt = 0; nt < 8; nt++) {
            o[nt][0] *= al0; o[nt][1] *= al0;
            o[nt][2] *= al1; o[nt][3] *= al1;
        }

        #pragma unroll
        for (int nt = 0; nt < 8; nt++) {
            *(float2*)&Ps[(w16 + g) * 72 + nt * 8 + 2 * tig] = make_float2(
                f2tf32f(s[nt][0]), f2tf32f(s[nt][1]));
            *(float2*)&Ps[(w16 + g + 8) * 72 + nt * 8 + 2 * tig] = make_float2(
                f2tf32f(s[nt][2]), f2tf32f(s[nt][3]));
        }
        __syncwarp();

        #pragma unroll
        for (int kk = 0; kk < 8; kk++) {
            const uint32_t pa0 = __float_as_uint(Ps[(w16 + g)     * 72 + kk * 8 + tig]);
            const uint32_t pa1 = __float_as_uint(Ps[(w16 + g + 8) * 72 + kk * 8 + tig]);
            const uint32_t pa2 = __float_as_uint(Ps[(w16 + g)     * 72 + kk * 8 + tig + 4]);
            const uint32_t pa3 = __float_as_uint(Ps[(w16 + g + 8) * 72 + kk * 8 + tig + 4]);
            #pragma unroll
            for (int nt = 0; nt < 8; nt++) {
                const uint32_t b0 =
                    __float_as_uint(Vs[(kk * 8 + tig)     * 72 + nt * 8 + g]);
                const uint32_t b1 =
                    __float_as_uint(Vs[(kk * 8 + tig + 4) * 72 + nt * 8 + g]);
                mma_tf32(o[nt], pa0, pa1, pa2, pa3, b0, b1);
            }
        }
        __syncwarp();
    }

    const float i0 = 1.f / l0;
    const float i1 = 1.f / l1;
    const size_t gr0 = (size_t)(b * S + q0 + w16 + g) * E + hoff;
    const size_t gr1 = gr0 + 8 * E;
    #pragma unroll
    for (int nt = 0; nt < 8; nt++) {
        const int cc = nt * 8 + 2 * tig;
        *(float2*)&y[gr0 + cc] = make_float2(o[nt][0] * i0, o[nt][1] * i0);
        *(float2*)&y[gr1 + cc] = make_float2(o[nt][2] * i1, o[nt][3] * i1);
    }
}

// ---------------------------------------------------------------------------
extern "C" void kernel_launch(void* const* d_in, const int* in_sizes, int n_in,
                              void* d_out, int out_size)
{
    const float* x      = (const float*)d_in[0];
    const float* w_attn = (const float*)d_in[1];
    const float* w_proj = (const float*)d_in[2];
    float* out = (float*)d_out;

    float *qkv, *yb, *xc, *wat, *wpt;
    cudaGetSymbolAddress((void**)&qkv, g_qkv);
    cudaGetSymbolAddress((void**)&yb,  g_y);
    cudaGetSymbolAddress((void**)&xc,  g_xc);
    cudaGetSymbolAddress((void**)&wat, g_wat);
    cudaGetSymbolAddress((void**)&wpt, g_wpt);

    cudaFuncSetAttribute(gemm_tc, cudaFuncAttributeMaxDynamicSharedMemorySize,
                         GEMM_SMEM);
    cudaFuncSetAttribute(attn_mma, cudaFuncAttributeMaxDynamicSharedMemorySize,
                         ATT_SMEM_BYTES);

    const int xChunks = BS * E / 4;

    // Pre-passes: cvt+permute x; transpose+cvt+permute weights.
    permute_cvt_k<<<(xChunks + 255) / 256, 256>>>(x, xc, xChunks, E);
    transpose_permute_k<<<dim3(E3 / 32, E / 32), dim3(32, 8)>>>(w_attn, wat, E, E3);
    transpose_permute_k<<<dim3(E / 32, E / 32), dim3(32, 8)>>>(w_proj, wpt, E, E);

    // 1) qkv = x @ w_attn   [4096, 3072]
    gemm_tc<<<dim3(E3 / 128, BS / 128), 256, GEMM_SMEM>>>(xc, wat, qkv, BS, E3, E);
    // 2) tensor-core flash attention -> y  [4096, 1024]
    attn_mma<<<dim3(S / 128, B * NHD), 256, ATT_SMEM_BYTES>>>(qkv, yb);
    // 3) out = y @ w_proj   [4096, 1024]   (y permuted into xc first)
    permute_cvt_k<<<(xChunks + 255) / 256, 256>>>(yb, xc, xChunks, E);
    gemm_tc<<<dim3(E / 128, BS / 128), 256, GEMM_SMEM>>>(xc, wpt, out, BS, E, E);
}

// round 10
// speedup vs baseline: 2.9321x; 1.0771x over previous
#include <cuda_runtime.h>
#include <cstdint>

// Shapes fixed by the problem: B=2, S=2048, E=1024, H=16, D=64.
static constexpr int E   = 1024;
static constexpr int NHD = 16;
static constexpr int HD  = 64;
static constexpr int B   = 2;
static constexpr int S   = 2048;
static constexpr int BS  = B * S;      // 4096 tokens
static constexpr int E3  = 3 * E;      // 3072

__device__ float g_qkv[(size_t)BS * E3];   // 48 MB
__device__ float g_xc[(size_t)BS * E];     // 16 MB  permuted x / permuted y
__device__ float g_wat[(size_t)E3 * E];    // 12 MB  w_attn^T, permuted
__device__ float g_wpt[(size_t)E * E];     //  4 MB  w_proj^T, permuted

// ---------------------------------------------------------------------------
// Helpers (mma.sync/cp.async are sm_80+ PTX: legal on compute_103; tcgen05
// is NOT — it needs the sm_103a target which this toolchain won't emit).
//
// GEMM operand layout ("quadset"): per row r, per 16-float k-group, chunk c
// holds quadset q = c ^ (r&3): elements k = q+4j at word j. One LDS.128 is a
// lane's m16n8k8 A/B fragment for 2 k-steps.
// ---------------------------------------------------------------------------
__device__ __forceinline__ uint32_t f2tf32(float f) {
    uint32_t u;
    asm("cvt.rna.tf32.f32 %0, %1;" : "=r"(u) : "f"(f));
    return u;
}
__device__ __forceinline__ float f2tf32f(float f) {
    return __uint_as_float(f2tf32(f));
}
__device__ __forceinline__ uint32_t smem_u32(const void* p) {
    uint32_t a;
    asm("{ .reg .u64 t; cvta.to.shared.u64 t, %1; cvt.u32.u64 %0, t; }"
        : "=r"(a) : "l"(p));
    return a;
}
__device__ __forceinline__ void cp16(uint32_t dst, const void* src) {
    asm volatile("cp.async.ca.shared.global [%0], [%1], 16;"
                 :: "r"(dst), "l"(src));
}
#define CP_COMMIT() asm volatile("cp.async.commit_group;" ::: "memory")
#define CP_WAIT2()  asm volatile("cp.async.wait_group 2;" ::: "memory")

// D = A(16x8, row) @ B(8x8, col) + C, tf32 in / f32 out.
__device__ __forceinline__ void mma_tf32(float* c, uint32_t a0, uint32_t a1,
                                         uint32_t a2, uint32_t a3,
                                         uint32_t b0, uint32_t b1) {
    asm volatile(
        "mma.sync.aligned.m16n8k8.row.col.f32.tf32.tf32.f32 "
        "{%0,%1,%2,%3}, {%4,%5,%6,%7}, {%8,%9}, {%0,%1,%2,%3};"
        : "+f"(c[0]), "+f"(c[1]), "+f"(c[2]), "+f"(c[3])
        : "r"(a0), "r"(a1), "r"(a2), "r"(a3), "r"(b0), "r"(b1));
}

// ---------------------------------------------------------------------------
// Pre-pass kernels (unchanged from R8).
// ---------------------------------------------------------------------------
__global__ void permute_cvt_k(const float* __restrict__ in,
                              float* __restrict__ out, int nChunks, int Kf) {
    const int idx = blockIdx.x * blockDim.x + threadIdx.x;
    if (idx >= nChunks) return;
    const int cpr = Kf >> 2;
    const int r = idx / cpr;
    const int pos = idx - r * cpr;
    const int gbase = (pos >> 2) << 4;
    const int c = pos & 3;
    const int q = c ^ (r & 3);
    const float* src = in + (size_t)r * Kf + gbase + q;
    ((float4*)out)[idx] = make_float4(f2tf32f(src[0]), f2tf32f(src[4]),
                                      f2tf32f(src[8]), f2tf32f(src[12]));
}

__global__ void transpose_permute_k(const float* __restrict__ in,
                                    float* __restrict__ out, int R, int Cc) {
    __shared__ float t[32][33];
    const int c0 = blockIdx.x * 32, r0 = blockIdx.y * 32;
    #pragma unroll
    for (int j = 0; j < 4; j++) {
        const int r = threadIdx.y + j * 8;
        t[r][threadIdx.x] = in[(size_t)(r0 + r) * Cc + c0 + threadIdx.x];
    }
    __syncthreads();
    const int x = threadIdx.x;
    #pragma unroll
    for (int j = 0; j < 4; j++) {
        const int nl = threadIdx.y + j * 8;
        const int src_kk = (x & 16) | ((((x >> 2) & 3) ^ (nl & 3)) + ((x & 3) << 2));
        out[(size_t)(c0 + nl) * R + r0 + x] = f2tf32f(t[src_kk][nl]);
    }
}

// ---------------------------------------------------------------------------
// Tensor-core tf32 GEMM (unchanged from R8).
// ---------------------------------------------------------------------------
static constexpr int GST_FLOATS = 2 * 128 * 16;             // 16 KB
static constexpr int GEMM_SMEM  = 4 * GST_FLOATS * 4;       // 65536 B

__global__ __launch_bounds__(256, 2) void gemm_tc(
    const float* __restrict__ At, const float* __restrict__ Bt,
    float* __restrict__ C, int M, int N, int K)
{
    extern __shared__ float smf[];
    const uint32_t sbase = smem_u32(smf);

    const int tid  = threadIdx.x;
    const int wid  = tid >> 5;
    const int lane = tid & 31;
    const int g    = lane >> 2;
    const int tig  = lane & 3;
    const int m0   = (wid >> 2) * 64;
    const int n0   = (wid & 3) * 32;
    const int brow = blockIdx.y * 128;
    const int bcol = blockIdx.x * 128;

    const int lr = tid >> 1;
    const int lc = (tid & 1) * 2;
    const float* gA = At + (size_t)(brow + lr) * K + lc * 4;
    const float* gB = Bt + (size_t)(bcol + lr) * K + lc * 4;
    const uint32_t dOff = (uint32_t)(lr * 64 + lc * 16);

    float acc[4][4][4];
    #pragma unroll
    for (int mt = 0; mt < 4; mt++)
        #pragma unroll
        for (int nt = 0; nt < 4; nt++)
            #pragma unroll
            for (int i = 0; i < 4; i++) acc[mt][nt][i] = 0.f;

    const int nIter = K >> 4;

    #define G_ISSUE(it) do {                                                  \
        const uint32_t _dA = sbase + ((it) & 3) * (GST_FLOATS * 4) + dOff;    \
        const float* _sa = gA + (it) * 16;                                    \
        const float* _sb = gB + (it) * 16;                                    \
        cp16(_dA,        _sa);                                                \
        cp16(_dA + 16,   _sa + 4);                                            \
        cp16(_dA + 8192, _sb);                                                \
        cp16(_dA + 8208, _sb + 4);                                            \
    } while (0)

    G_ISSUE(0); CP_COMMIT();
    G_ISSUE(1); CP_COMMIT();

    for (int it = 0; it < nIter; ++it) {
        if (it + 2 < nIter) G_ISSUE(it + 2);
        CP_COMMIT();
        CP_WAIT2();
        __syncthreads();

        const float* SA = smf + (it & 3) * GST_FLOATS;
        const float* SB = SA + 2048;

        float4 bF[4];
        #pragma unroll
        for (int nt = 0; nt < 4; nt++) {
            const int n = n0 + nt * 8 + g;
            bF[nt] = *(const float4*)&SB[n * 16 + ((tig ^ (n & 3)) << 2)];
        }
        #pragma unroll
        for (int mt = 0; mt < 4; mt++) {
            const int ma = m0 + mt * 16 + g;
            const float4 a0v = *(const float4*)&SA[ma * 16 + ((tig ^ (ma & 3)) << 2)];
            const float4 a1v = *(const float4*)&SA[(ma + 8) * 16 + ((tig ^ (ma & 3)) << 2)];
            #pragma unroll
            for (int nt = 0; nt < 4; nt++)
                mma_tf32(acc[mt][nt],
                         __float_as_uint(a0v.x), __float_as_uint(a1v.x),
                         __float_as_uint(a0v.y), __float_as_uint(a1v.y),
                         __float_as_uint(bF[nt].x), __float_as_uint(bF[nt].y));
            #pragma unroll
            for (int nt = 0; nt < 4; nt++)
                mma_tf32(acc[mt][nt],
                         __float_as_uint(a0v.z), __float_as_uint(a1v.z),
                         __float_as_uint(a0v.w), __float_as_uint(a1v.w),
                         __float_as_uint(bF[nt].z), __float_as_uint(bF[nt].w));
        }
    }
    #undef G_ISSUE

    #pragma unroll
    for (int mt = 0; mt < 4; mt++) {
        #pragma unroll
        for (int nt = 0; nt < 4; nt++) {
            const int r0 = brow + m0 + mt * 16 + g;
            const int cc = bcol + n0 + nt * 8 + 2 * tig;
            *(float2*)&C[(size_t)r0 * N + cc] =
                make_float2(acc[mt][nt][0], acc[mt][nt][1]);
            *(float2*)&C[(size_t)(r0 + 8) * N + cc] =
                make_float2(acc[mt][nt][2], acc[mt][nt][3]);
        }
    }
}

// ---------------------------------------------------------------------------
// Tensor-core flash attention, v2: vectorized K / V fragment loads.
//   Ks: [64 key rows][d quadset], row stride 80.
//       addr(r,d) = r*80 + (d>>4)*16 + (((d&3)^(r&3))<<2) + ((d>>2)&3)
//   Vs: [64 key rows][d column-permuted], row stride 72.
//       pos(d) = 4*(d&7) + 32*(d>>5) + ((d>>3)&3)
//       -> float4 at 4g+32q = PV b0 fragments for nt=4q..4q+3.
// Epilogue writes y directly in the proj-GEMM's permuted tf32 layout.
// ---------------------------------------------------------------------------
static constexpr int ATT_Q_FLOATS = 128 * 72;   // Qs (reused as Ps)
static constexpr int ATT_K_FLOATS = 64 * 80;
static constexpr int ATT_V_FLOATS = 64 * 72;
static constexpr int ATT_SMEM_BYTES =
    (ATT_Q_FLOATS + ATT_K_FLOATS + ATT_V_FLOATS) * 4;     // 75,776 B

__global__ __launch_bounds__(256) void attn_mma(
    const float* __restrict__ qkv, float* __restrict__ yperm)
{
    extern __shared__ float sm[];
    float* Qs = sm;
    float* Ks = sm + ATT_Q_FLOATS;
    float* Vs = Ks + ATT_K_FLOATS;
    float* Ps = Qs;

    const int qt  = blockIdx.x;
    const int bh  = blockIdx.y;
    const int b   = bh >> 4;
    const int h   = bh & 15;
    const int q0  = qt * 128;
    const int tid = threadIdx.x;
    const int wid = tid >> 5;
    const int lane = tid & 31;
    const int g   = lane >> 2;
    const int tig = lane & 3;
    const int w16 = wid * 16;

    const float* base = qkv + (size_t)b * S * E3;
    const int hoff = h * HD;

    // Stage Q (scale folded, tf32), plain [row][72] layout.
    #pragma unroll
    for (int rep = 0; rep < 8; rep++) {
        const int idx = rep * 256 + tid;
        const int r = idx >> 4, d4 = (idx & 15) << 2;
        float4 v = *(const float4*)&base[(size_t)(q0 + r) * E3 + hoff + d4];
        *(float4*)&Qs[r * 72 + d4] = make_float4(
            f2tf32f(v.x * 0.125f), f2tf32f(v.y * 0.125f),
            f2tf32f(v.z * 0.125f), f2tf32f(v.w * 0.125f));
    }
    __syncthreads();

    uint32_t qa[8][4];
    #pragma unroll
    for (int kk = 0; kk < 8; kk++) {
        qa[kk][0] = __float_as_uint(Qs[(w16 + g)     * 72 + kk * 8 + tig]);
        qa[kk][1] = __float_as_uint(Qs[(w16 + g + 8) * 72 + kk * 8 + tig]);
        qa[kk][2] = __float_as_uint(Qs[(w16 + g)     * 72 + kk * 8 + tig + 4]);
        qa[kk][3] = __float_as_uint(Qs[(w16 + g + 8) * 72 + kk * 8 + tig + 4]);
    }
    __syncthreads();   // Qs now reusable as Ps

    float o[8][4];
    #pragma unroll
    for (int nt = 0; nt < 8; nt++)
        #pragma unroll
        for (int i = 0; i < 4; i++) o[nt][i] = 0.f;
    float m0v = -1e30f, m1v = -1e30f, l0 = 0.f, l1 = 0.f;

    const int row0g = q0 + w16 + g;
    const int nkt = 2 * qt + 2;

    for (int kt = 0; kt < nkt; kt++) {
        const int kbase = kt * 64;
        __syncthreads();
        // Stage K (quadset) and V (column-permuted), tf32, scalar scatter.
        #pragma unroll
        for (int rep = 0; rep < 4; rep++) {
            const int idx = rep * 256 + tid;
            const int r = idx >> 4, d4 = (idx & 15) << 2;
            const float* src = &base[(size_t)(kbase + r) * E3 + E + hoff + d4];
            float4 kv = *(const float4*)src;
            float4 vv = *(const float4*)(src + E);
            const float ka[4] = {kv.x, kv.y, kv.z, kv.w};
            const float va[4] = {vv.x, vv.y, vv.z, vv.w};
            const int kb = r * 80 + ((d4 >> 4) << 4) + ((d4 >> 2) & 3);
            const int vb = r * 72 + ((d4 >> 5) << 5) + ((d4 >> 3) & 3);
            #pragma unroll
            for (int e = 0; e < 4; e++) {
                Ks[kb + ((e ^ (r & 3)) << 2)] = f2tf32f(ka[e]);
                Vs[vb + (((d4 + e) & 7) << 2)] = f2tf32f(va[e]);
            }
        }
        __syncthreads();

        // S = Q @ K^T : per (gr, nt) one LDS.128 covers k-steps 2gr, 2gr+1.
        float s[8][4];
        #pragma unroll
        for (int nt = 0; nt < 8; nt++)
            #pragma unroll
            for (int i = 0; i < 4; i++) s[nt][i] = 0.f;

        #pragma unroll
        for (int gr = 0; gr < 4; gr++) {
            #pragma unroll
            for (int nt = 0; nt < 8; nt++) {
                const int n = nt * 8 + g;
                const float4 kf = *(const float4*)&Ks[n * 80 + gr * 16 +
                                                      ((tig ^ (n & 3)) << 2)];
                mma_tf32(s[nt], qa[2 * gr][0], qa[2 * gr][1],
                         qa[2 * gr][2], qa[2 * gr][3],
                         __float_as_uint(kf.x), __float_as_uint(kf.y));
                mma_tf32(s[nt], qa[2 * gr + 1][0], qa[2 * gr + 1][1],
                         qa[2 * gr + 1][2], qa[2 * gr + 1][3],
                         __float_as_uint(kf.z), __float_as_uint(kf.w));
            }
        }

        if (kt >= 2 * qt) {
            #pragma unroll
            for (int nt = 0; nt < 8; nt++) {
                const int key = kbase + nt * 8 + 2 * tig;
                if (key     > row0g)     s[nt][0] = -1e30f;
                if (key + 1 > row0g)     s[nt][1] = -1e30f;
                if (key     > row0g + 8) s[nt][2] = -1e30f;
                if (key + 1 > row0g + 8) s[nt][3] = -1e30f;
            }
        }

        float mx0 = -1e30f, mx1 = -1e30f;
        #pragma unroll
        for (int nt = 0; nt < 8; nt++) {
            mx0 = fmaxf(mx0, fmaxf(s[nt][0], s[nt][1]));
            mx1 = fmaxf(mx1, fmaxf(s[nt][2], s[nt][3]));
        }
        #pragma unroll
        for (int off = 1; off <= 2; off <<= 1) {
            mx0 = fmaxf(mx0, __shfl_xor_sync(0xffffffffu, mx0, off));
            mx1 = fmaxf(mx1, __shfl_xor_sync(0xffffffffu, mx1, off));
        }
        const float nm0 = fmaxf(m0v, mx0);
        const float nm1 = fmaxf(m1v, mx1);
        const float al0 = __expf(m0v - nm0);
        const float al1 = __expf(m1v - nm1);
        m0v = nm0; m1v = nm1;
        float rs0 = 0.f, rs1 = 0.f;
        #pragma unroll
        for (int nt = 0; nt < 8; nt++) {
            s[nt][0] = __expf(s[nt][0] - nm0); rs0 += s[nt][0];
            s[nt][1] = __expf(s[nt][1] - nm0); rs0 += s[nt][1];
            s[nt][2] = __expf(s[nt][2] - nm1); rs1 += s[nt][2];
            s[nt][3] = __expf(s[nt][3] - nm1); rs1 += s[nt][3];
        }
        #pragma unroll
        for (int off = 1; off <= 2; off <<= 1) {
            rs0 += __shfl_xor_sync(0xffffffffu, rs0, off);
            rs1 += __shfl_xor_sync(0xffffffffu, rs1, off);
        }
        l0 = l0 * al0 + rs0;
        l1 = l1 * al1 + rs1;
        #pragma unroll
        for (int nt = 0; nt < 8; nt++) {
            o[nt][0] *= al0; o[nt][1] *= al0;
            o[nt][2] *= al1; o[nt][3] *= al1;
        }

        // P -> smem (tf32, warp-private rows, plain layout).
        #pragma unroll
        for (int nt = 0; nt < 8; nt++) {
            *(float2*)&Ps[(w16 + g) * 72 + nt * 8 + 2 * tig] = make_float2(
                f2tf32f(s[nt][0]), f2tf32f(s[nt][1]));
            *(float2*)&Ps[(w16 + g + 8) * 72 + nt * 8 + 2 * tig] = make_float2(
                f2tf32f(s[nt][2]), f2tf32f(s[nt][3]));
        }
        __syncwarp();

        // O += P @ V : per kk, 4 LDS.128 give b0/b1 for all 8 nt.
        #pragma unroll
        for (int kk = 0; kk < 8; kk++) {
            const uint32_t pa0 = __float_as_uint(Ps[(w16 + g)     * 72 + kk * 8 + tig]);
            const uint32_t pa1 = __float_as_uint(Ps[(w16 + g + 8) * 72 + kk * 8 + tig]);
            const uint32_t pa2 = __float_as_uint(Ps[(w16 + g)     * 72 + kk * 8 + tig + 4]);
            const uint32_t pa3 = __float_as_uint(Ps[(w16 + g + 8) * 72 + kk * 8 + tig + 4]);
            const float* r0p = &Vs[(kk * 8 + tig) * 72 + 4 * g];
            const float* r1p = r0p + 4 * 72;
            const float4 v0a = *(const float4*)r0p;
            const float4 v0b = *(const float4*)(r0p + 32);
            const float4 v1a = *(const float4*)r1p;
            const float4 v1b = *(const float4*)(r1p + 32);
            const float b0a[8] = {v0a.x, v0a.y, v0a.z, v0a.w,
                                  v0b.x, v0b.y, v0b.z, v0b.w};
            const float b1a[8] = {v1a.x, v1a.y, v1a.z, v1a.w,
                                  v1b.x, v1b.y, v1b.z, v1b.w};
            #pragma unroll
            for (int nt = 0; nt < 8; nt++)
                mma_tf32(o[nt], pa0, pa1, pa2, pa3,
                         __float_as_uint(b0a[nt]), __float_as_uint(b1a[nt]));
        }
        __syncwarp();
    }

    // Epilogue: normalize + write y DIRECTLY in permuted tf32 layout (proj A).
    const float i0 = 1.f / l0;
    const float i1 = 1.f / l1;
    const int rg0 = b * S + q0 + w16 + g;      // (rg0+8)&3 == rg0&3
    #pragma unroll
    for (int nt = 0; nt < 8; nt++) {
        #pragma unroll
        for (int i = 0; i < 2; i++) {
            const int col = hoff + nt * 8 + 2 * tig + i;
            const size_t a0 = (size_t)rg0 * E + ((col >> 4) << 4) +
                              (((col & 3) ^ (rg0 & 3)) << 2) + ((col >> 2) & 3);
            yperm[a0]            = f2tf32f(o[nt][i]     * i0);
            yperm[a0 + 8 * E]    = f2tf32f(o[nt][i + 2] * i1);
        }
    }
}

// ---------------------------------------------------------------------------
extern "C" void kernel_launch(void* const* d_in, const int* in_sizes, int n_in,
                              void* d_out, int out_size)
{
    const float* x      = (const float*)d_in[0];
    const float* w_attn = (const float*)d_in[1];
    const float* w_proj = (const float*)d_in[2];
    float* out = (float*)d_out;

    float *qkv, *xc, *wat, *wpt;
    cudaGetSymbolAddress((void**)&qkv, g_qkv);
    cudaGetSymbolAddress((void**)&xc,  g_xc);
    cudaGetSymbolAddress((void**)&wat, g_wat);
    cudaGetSymbolAddress((void**)&wpt, g_wpt);

    cudaFuncSetAttribute(gemm_tc, cudaFuncAttributeMaxDynamicSharedMemorySize,
                         GEMM_SMEM);
    cudaFuncSetAttribute(attn_mma, cudaFuncAttributeMaxDynamicSharedMemorySize,
                         ATT_SMEM_BYTES);

    const int xChunks = BS * E / 4;

    // Pre-passes: cvt+permute x; transpose+cvt+permute weights.
    permute_cvt_k<<<(xChunks + 255) / 256, 256>>>(x, xc, xChunks, E);
    transpose_permute_k<<<dim3(E3 / 32, E / 32), dim3(32, 8)>>>(w_attn, wat, E, E3);
    transpose_permute_k<<<dim3(E / 32, E / 32), dim3(32, 8)>>>(w_proj, wpt, E, E);

    // 1) qkv = x @ w_attn   [4096, 3072]
    gemm_tc<<<dim3(E3 / 128, BS / 128), 256, GEMM_SMEM>>>(xc, wat, qkv, BS, E3, E);
    // 2) flash attention -> permuted y (written straight into proj-A layout)
    attn_mma<<<dim3(S / 128, B * NHD), 256, ATT_SMEM_BYTES>>>(qkv, xc);
    // 3) out = y @ w_proj   [4096, 1024]
    gemm_tc<<<dim3(E / 128, BS / 128), 256, GEMM_SMEM>>>(xc, wpt, out, BS, E, E);
}